// round 1
// baseline (speedup 1.0000x reference)
#include <cuda_runtime.h>

#define Bn 64
#define Cn 128
#define Ln 400
#define Hn 8
#define DKn 16
#define Kn 7
#define CLn (Cn*Ln)            // 51200
#define BCL (Bn*Cn*Ln)         // 3276800
#define EPSf 1e-5f
#define LTILE 32
#define NLT 13                 // ceil(400/32)

// ---------------- scratch (static device arrays; no allocation) ----------------
__device__ float g_bufA[BCL];
__device__ float g_bufB[BCL];
__device__ float g_scr[BCL];     // attention output (B,C,L)
__device__ float g_q[BCL];       // (B,H,L,DK)
__device__ float g_k[BCL];
__device__ float g_v[BCL];
__device__ float g_part[Bn*64*2];  // per-(batch, block-tile) partial [sum, sumsq]
__device__ float g_muvar[2*Bn];    // mu[b], rsigma[b]

// ---------------- packed f32x2 helpers ----------------
typedef unsigned long long u64;
__device__ __forceinline__ u64 pack2(float lo, float hi){
    u64 r; asm("mov.b64 %0, {%1,%2};" : "=l"(r) : "f"(lo), "f"(hi)); return r;
}
__device__ __forceinline__ void unpack2(u64 v, float& lo, float& hi){
    asm("mov.b64 {%0,%1}, %2;" : "=f"(lo), "=f"(hi) : "l"(v));
}
__device__ __forceinline__ u64 fma2(u64 a, u64 b, u64 c){
    u64 d; asm("fma.rn.f32x2 %0, %1, %2, %3;" : "=l"(d) : "l"(a), "l"(b), "l"(c)); return d;
}
__device__ __forceinline__ u64 mul2(u64 a, u64 b){
    u64 d; asm("mul.rn.f32x2 %0, %1, %2;" : "=l"(d) : "l"(a), "l"(b)); return d;
}

// deterministic 2-value block reduction (256 threads), writes [sum,sumsq] to out2
__device__ __forceinline__ void block_reduce2(float s, float ss, float* out2, float* red){
    #pragma unroll
    for (int o = 16; o > 0; o >>= 1){
        s  += __shfl_down_sync(0xffffffffu, s,  o);
        ss += __shfl_down_sync(0xffffffffu, ss, o);
    }
    int w = threadIdx.x >> 5;
    if ((threadIdx.x & 31) == 0){ red[w*2] = s; red[w*2+1] = ss; }
    __syncthreads();
    if (threadIdx.x == 0){
        float a = 0.f, b = 0.f;
        int nw = blockDim.x >> 5;
        for (int i = 0; i < nw; i++){ a += red[i*2]; b += red[i*2+1]; }
        out2[0] = a; out2[1] = b;
    }
}

// ---------------- kernel: x + positional encoding, + LN partial stats ----------------
// grid (B, 50), block 256 ; each thread one float4 (400 % 4 == 0 so one c per float4)
__global__ __launch_bounds__(256) void k_pos(const float* __restrict__ x){
    int b  = blockIdx.x;
    int i4 = blockIdx.y * 256 + threadIdx.x;          // 0..12799
    float4 xv = ((const float4*)x)[b*(CLn/4) + i4];
    int e0 = i4 * 4;
    int c  = e0 / Ln;
    int l  = e0 - c * Ln;
    float fc, ph;
    if ((c & 1) == 0){ fc =  powf(10000.f, -(float)c / 128.f);        ph = 0.f; }
    else             { fc = -powf(10000.f, (1.f - (float)c) / 128.f); ph = 1.5707963267948966f; }
    float v0 = xv.x + sinf((float)(l+0)*fc + ph);
    float v1 = xv.y + sinf((float)(l+1)*fc + ph);
    float v2 = xv.z + sinf((float)(l+2)*fc + ph);
    float v3 = xv.w + sinf((float)(l+3)*fc + ph);
    ((float4*)g_bufA)[b*(CLn/4) + i4] = make_float4(v0, v1, v2, v3);
    float s  = v0 + v1 + v2 + v3;
    float ss = v0*v0 + v1*v1 + v2*v2 + v3*v3;
    __shared__ float red[16];
    block_reduce2(s, ss, &g_part[(b*64 + blockIdx.y)*2], red);
}

// ---------------- kernel: finalize LN stats ----------------
__global__ void k_fin(int nparts){
    int b = threadIdx.x;
    if (b >= Bn) return;
    float s = 0.f, ss = 0.f;
    for (int i = 0; i < nparts; i++){ s += g_part[(b*64+i)*2]; ss += g_part[(b*64+i)*2+1]; }
    float mu  = s  / (float)CLn;
    float var = ss / (float)CLn - mu*mu;
    g_muvar[b]     = mu;
    g_muvar[Bn+b]  = rsqrtf(var + EPSf);
}

// ---------------- fused conv layer: LN -> depthwise -> pointwise -> relu -> +res -> stats ----
// grid (B, NLT), block 256
#define CONV_SMEM_F (16896 + 5120 + 4224 + 1024 + 128 + 16)
__global__ __launch_bounds__(256) void k_conv(
        const float* __restrict__ in, float* __restrict__ out,
        const float* __restrict__ dw, const float* __restrict__ db,
        const float* __restrict__ pw, const float* __restrict__ pb,
        const float* __restrict__ lng, const float* __restrict__ lnb){
    extern __shared__ float sm[];
    float* Wsm = sm;                 // [c][o] pitch 132 : 16896
    float* Xsm = Wsm + 16896;        // [c][38] pitch 40 : 5120 (LN'ed input + halo)
    float* Ysm = Xsm + 5120;         // [c][32] pitch 33 : 4224 (depthwise out)
    float* Dw  = Ysm + 4224;         // [c][7] pitch 8   : 1024
    float* Db  = Dw  + 1024;         // 128
    float* red = Db  + 128;          // 16
    int b = blockIdx.x, lt = blockIdx.y, tid = threadIdx.x;
    int l0 = lt * LTILE;
    float mu = g_muvar[b], rs = g_muvar[Bn + b];

    for (int idx = tid; idx < Cn*Cn; idx += 256){
        int o = idx >> 7, c = idx & 127;
        Wsm[c*132 + o] = pw[idx];
    }
    for (int idx = tid; idx < Cn*Kn; idx += 256)
        Dw[(idx/7)*8 + (idx - (idx/7)*7)] = dw[idx];
    if (tid < Cn) Db[tid] = db[tid];
    for (int idx = tid; idx < Cn*38; idx += 256){
        int c = idx / 38, j = idx - c*38;
        int gl = l0 - 3 + j;
        float v = 0.f;
        if (gl >= 0 && gl < Ln){
            int gi = (b*Cn + c)*Ln + gl;
            v = (in[gi] - mu)*rs*lng[c*Ln + gl] + lnb[c*Ln + gl];
        }
        Xsm[c*40 + j] = v;
    }
    __syncthreads();
    for (int idx = tid; idx < Cn*LTILE; idx += 256){
        int c = idx >> 5, l = idx & 31;
        float a = Db[c];
        #pragma unroll
        for (int t = 0; t < 7; t++) a += Xsm[c*40 + l + t] * Dw[c*8 + t];
        Ysm[c*33 + l] = a;
    }
    __syncthreads();

    int tx = tid & 31, ty = tid >> 5, ob = ty*16;
    u64 acc[8];
    #pragma unroll
    for (int k = 0; k < 8; k++) acc[k] = pack2(0.f, 0.f);
    #pragma unroll 4
    for (int c = 0; c < Cn; c++){
        float y = Ysm[c*33 + tx];
        u64 y2 = pack2(y, y);
        const ulonglong2* wp = (const ulonglong2*)(Wsm + c*132 + ob);
        ulonglong2 wa = wp[0], wb = wp[1], wc = wp[2], wd = wp[3];
        acc[0] = fma2(wa.x, y2, acc[0]); acc[1] = fma2(wa.y, y2, acc[1]);
        acc[2] = fma2(wb.x, y2, acc[2]); acc[3] = fma2(wb.y, y2, acc[3]);
        acc[4] = fma2(wc.x, y2, acc[4]); acc[5] = fma2(wd.x, y2, acc[5]);
        acc[6] = fma2(wc.y, y2, acc[6]); acc[7] = fma2(wd.y, y2, acc[7]);
    }
    // note: acc[4]<->wc.x, acc[5]<->wd.x, acc[6]<->wc.y, acc[7]<->wd.y (remap below)
    int gl = l0 + tx;
    float s = 0.f, ss = 0.f;
    if (gl < Ln){
        // mapping of accumulators to output channel pairs:
        // acc[0]:(0,1) acc[1]:(2,3) acc[2]:(4,5) acc[3]:(6,7)
        // acc[4]:(8,9) acc[6]:(10,11) acc[5]:(12,13) acc[7]:(14,15)
        int omap[8] = {0, 2, 4, 6, 8, 12, 10, 14};
        #pragma unroll
        for (int k = 0; k < 8; k++){
            float z0, z1; unpack2(acc[k], z0, z1);
            int o0 = ob + omap[k];
            z0 += pb[o0]; z1 += pb[o0+1];
            z0 = z0 > 0.f ? z0 : 0.f;  z1 = z1 > 0.f ? z1 : 0.f;
            float r0 = in[(b*Cn + o0  )*Ln + gl];
            float r1 = in[(b*Cn + o0+1)*Ln + gl];
            float v0 = r0 + z0, v1 = r1 + z1;
            out[(b*Cn + o0  )*Ln + gl] = v0;
            out[(b*Cn + o0+1)*Ln + gl] = v1;
            s += v0 + v1; ss += v0*v0 + v1*v1;
        }
    }
    block_reduce2(s, ss, &g_part[(b*64 + lt)*2], red);
}

// ---------------- generic matmul: out = resid + [relu](W @ [LN](in) + bias) ----------------
// grid (B, NLT), block 256
#define MM_SMEM_F (16896 + 4224 + 16)
template<bool LN, bool RELU, bool STATS>
__global__ __launch_bounds__(256) void k_mm(
        const float* __restrict__ in, const float* resid, float* __restrict__ out,
        const float* __restrict__ W, const float* __restrict__ bias,
        const float* __restrict__ lng, const float* __restrict__ lnb){
    extern __shared__ float sm[];
    float* Wsm = sm;                 // [c][o] pitch 132
    float* Xsm = Wsm + 16896;        // [c][32] pitch 33
    float* red = Xsm + 4224;
    int b = blockIdx.x, lt = blockIdx.y, tid = threadIdx.x;
    int l0 = lt * LTILE;
    float mu = 0.f, rs = 1.f;
    if (LN){ mu = g_muvar[b]; rs = g_muvar[Bn + b]; }
    for (int idx = tid; idx < Cn*Cn; idx += 256){
        int o = idx >> 7, c = idx & 127;
        Wsm[c*132 + o] = W[idx];
    }
    for (int idx = tid; idx < Cn*LTILE; idx += 256){
        int c = idx >> 5, j = idx & 31;
        int gl = l0 + j;
        float v = 0.f;
        if (gl < Ln){
            v = in[(b*Cn + c)*Ln + gl];
            if (LN) v = (v - mu)*rs*lng[c*Ln + gl] + lnb[c*Ln + gl];
        }
        Xsm[c*33 + j] = v;
    }
    __syncthreads();
    int tx = tid & 31, ty = tid >> 5, ob = ty*16;
    u64 acc[8];
    #pragma unroll
    for (int k = 0; k < 8; k++) acc[k] = pack2(0.f, 0.f);
    #pragma unroll 4
    for (int c = 0; c < Cn; c++){
        float y = Xsm[c*33 + tx];
        u64 y2 = pack2(y, y);
        const ulonglong2* wp = (const ulonglong2*)(Wsm + c*132 + ob);
        ulonglong2 wa = wp[0], wb = wp[1], wc = wp[2], wd = wp[3];
        acc[0] = fma2(wa.x, y2, acc[0]); acc[1] = fma2(wa.y, y2, acc[1]);
        acc[2] = fma2(wb.x, y2, acc[2]); acc[3] = fma2(wb.y, y2, acc[3]);
        acc[4] = fma2(wc.x, y2, acc[4]); acc[5] = fma2(wd.x, y2, acc[5]);
        acc[6] = fma2(wc.y, y2, acc[6]); acc[7] = fma2(wd.y, y2, acc[7]);
    }
    int gl = l0 + tx;
    float s = 0.f, ss = 0.f;
    if (gl < Ln){
        int omap[8] = {0, 2, 4, 6, 8, 12, 10, 14};
        #pragma unroll
        for (int k = 0; k < 8; k++){
            float z0, z1; unpack2(acc[k], z0, z1);
            int o0 = ob + omap[k];
            z0 += bias[o0]; z1 += bias[o0+1];
            if (RELU){ z0 = z0 > 0.f ? z0 : 0.f;  z1 = z1 > 0.f ? z1 : 0.f; }
            float v0 = resid[(b*Cn + o0  )*Ln + gl] + z0;
            float v1 = resid[(b*Cn + o0+1)*Ln + gl] + z1;
            out[(b*Cn + o0  )*Ln + gl] = v0;
            out[(b*Cn + o0+1)*Ln + gl] = v1;
            if (STATS){ s += v0 + v1; ss += v0*v0 + v1*v1; }
        }
    }
    if (STATS) block_reduce2(s, ss, &g_part[(b*64 + lt)*2], red);
}

// ---------------- QKV projections (with LN on input), writes (B,H,L,DK) ----------------
// grid (B, NLT, 3)
__global__ __launch_bounds__(256) void k_qkv(
        const float* __restrict__ in,
        const float* __restrict__ wq, const float* __restrict__ bq,
        const float* __restrict__ wk, const float* __restrict__ bk,
        const float* __restrict__ wv, const float* __restrict__ bv,
        const float* __restrict__ lng, const float* __restrict__ lnb){
    extern __shared__ float sm[];
    float* Wsm = sm;
    float* Xsm = Wsm + 16896;
    int which = blockIdx.z;
    const float* W    = which == 0 ? wq : (which == 1 ? wk : wv);
    const float* bias = which == 0 ? bq : (which == 1 ? bk : bv);
    float* outp       = which == 0 ? g_q : (which == 1 ? g_k : g_v);
    float scale = which == 0 ? 0.08838834764831845f : 1.f;   // 1/sqrt(C)
    int b = blockIdx.x, lt = blockIdx.y, tid = threadIdx.x;
    int l0 = lt * LTILE;
    float mu = g_muvar[b], rs = g_muvar[Bn + b];
    for (int idx = tid; idx < Cn*Cn; idx += 256){
        int o = idx >> 7, c = idx & 127;
        Wsm[c*132 + o] = W[idx];
    }
    for (int idx = tid; idx < Cn*LTILE; idx += 256){
        int c = idx >> 5, j = idx & 31;
        int gl = l0 + j;
        float v = 0.f;
        if (gl < Ln)
            v = (in[(b*Cn + c)*Ln + gl] - mu)*rs*lng[c*Ln + gl] + lnb[c*Ln + gl];
        Xsm[c*33 + j] = v;
    }
    __syncthreads();
    int tx = tid & 31, ty = tid >> 5, ob = ty*16;
    u64 acc[8];
    #pragma unroll
    for (int k = 0; k < 8; k++) acc[k] = pack2(0.f, 0.f);
    #pragma unroll 4
    for (int c = 0; c < Cn; c++){
        float y = Xsm[c*33 + tx];
        u64 y2 = pack2(y, y);
        const ulonglong2* wp = (const ulonglong2*)(Wsm + c*132 + ob);
        ulonglong2 wa = wp[0], wb = wp[1], wc = wp[2], wd = wp[3];
        acc[0] = fma2(wa.x, y2, acc[0]); acc[1] = fma2(wa.y, y2, acc[1]);
        acc[2] = fma2(wb.x, y2, acc[2]); acc[3] = fma2(wb.y, y2, acc[3]);
        acc[4] = fma2(wc.x, y2, acc[4]); acc[5] = fma2(wd.x, y2, acc[5]);
        acc[6] = fma2(wc.y, y2, acc[6]); acc[7] = fma2(wd.y, y2, acc[7]);
    }
    int gl = l0 + tx;
    if (gl < Ln){
        int omap[8] = {0, 2, 4, 6, 8, 12, 10, 14};
        // h = ty (ob = ty*16 and all 16 outputs share the head)
        float* op = outp + ((size_t)(b*Hn + ty)*Ln + gl)*16;
        #pragma unroll
        for (int k = 0; k < 8; k++){
            float z0, z1; unpack2(acc[k], z0, z1);
            int d0 = omap[k];
            op[d0  ] = (z0 + bias[ob + d0    ])*scale;
            op[d0+1] = (z1 + bias[ob + d0 + 1])*scale;
        }
    }
}

// ---------------- attention: per (b,h), online softmax, K/V in smem ----------------
// grid (B*H), block 256 ; 2 query rows/thread
#define ATTN_SMEM_F (Ln*16 + Ln*16 + Ln)
__global__ __launch_bounds__(256) void k_attn(const float* __restrict__ mask){
    extern __shared__ float sm[];
    float* Ksm = sm;
    float* Vsm = Ksm + Ln*16;
    float* Msm = Vsm + Ln*16;
    int bh = blockIdx.x;
    int b = bh >> 3, h = bh & 7;
    int tid = threadIdx.x;
    const float4* kp = (const float4*)(g_k + (size_t)bh*Ln*16);
    const float4* vp = (const float4*)(g_v + (size_t)bh*Ln*16);
    for (int i = tid; i < Ln*4; i += 256){
        ((float4*)Ksm)[i] = kp[i];
        ((float4*)Vsm)[i] = vp[i];
    }
    for (int i = tid; i < Ln; i += 256) Msm[i] = mask[b*Ln + i];
    __syncthreads();

    int r0 = tid, r1 = tid + 256;
    bool ok1 = (r1 < Ln);
    u64 q0[8], q1[8];
    {
        const u64* qp = (const u64*)(g_q + ((size_t)bh*Ln + r0)*16);
        #pragma unroll
        for (int i = 0; i < 8; i++) q0[i] = qp[i];
    }
    if (ok1){
        const u64* qp = (const u64*)(g_q + ((size_t)bh*Ln + r1)*16);
        #pragma unroll
        for (int i = 0; i < 8; i++) q1[i] = qp[i];
    } else {
        #pragma unroll
        for (int i = 0; i < 8; i++) q1[i] = pack2(0.f, 0.f);
    }

    float m0 = -3.0e38f, m1 = -3.0e38f, den0 = 0.f, den1 = 0.f;
    u64 a0[8], a1[8];
    #pragma unroll
    for (int i = 0; i < 8; i++){ a0[i] = pack2(0.f,0.f); a1[i] = pack2(0.f,0.f); }

    for (int j = 0; j < Ln; j++){
        const ulonglong2* kr = (const ulonglong2*)(Ksm + j*16);
        ulonglong2 ka = kr[0], kb = kr[1], kc = kr[2], kd = kr[3];
        // dot products (packed)
        u64 s2;
        s2 = mul2(q0[0], ka.x);      s2 = fma2(q0[1], ka.y, s2);
        s2 = fma2(q0[2], kb.x, s2);  s2 = fma2(q0[3], kb.y, s2);
        s2 = fma2(q0[4], kc.x, s2);  s2 = fma2(q0[5], kc.y, s2);
        s2 = fma2(q0[6], kd.x, s2);  s2 = fma2(q0[7], kd.y, s2);
        float lo, hi; unpack2(s2, lo, hi);
        float s0 = lo + hi;
        s2 = mul2(q1[0], ka.x);      s2 = fma2(q1[1], ka.y, s2);
        s2 = fma2(q1[2], kb.x, s2);  s2 = fma2(q1[3], kb.y, s2);
        s2 = fma2(q1[4], kc.x, s2);  s2 = fma2(q1[5], kc.y, s2);
        s2 = fma2(q1[6], kd.x, s2);  s2 = fma2(q1[7], kd.y, s2);
        unpack2(s2, lo, hi);
        float s1v = lo + hi;

        float mk  = Msm[j];
        float adj = (1.f - mk)*(-1e30f);
        s0  = s0 *mk + adj;
        s1v = s1v*mk + adj;

        const ulonglong2* vr = (const ulonglong2*)(Vsm + j*16);
        ulonglong2 va = vr[0], vb = vr[1], vc = vr[2], vd = vr[3];

        // row 0 online softmax
        if (s0 > m0){
            float f = __expf(m0 - s0);
            u64 f2 = pack2(f, f);
            #pragma unroll
            for (int i = 0; i < 8; i++) a0[i] = mul2(a0[i], f2);
            den0 *= f; m0 = s0;
        }
        float p0 = __expf(s0 - m0);
        den0 += p0;
        u64 p02 = pack2(p0, p0);
        a0[0] = fma2(va.x, p02, a0[0]); a0[1] = fma2(va.y, p02, a0[1]);
        a0[2] = fma2(vb.x, p02, a0[2]); a0[3] = fma2(vb.y, p02, a0[3]);
        a0[4] = fma2(vc.x, p02, a0[4]); a0[5] = fma2(vc.y, p02, a0[5]);
        a0[6] = fma2(vd.x, p02, a0[6]); a0[7] = fma2(vd.y, p02, a0[7]);

        // row 1
        if (s1v > m1){
            float f = __expf(m1 - s1v);
            u64 f2 = pack2(f, f);
            #pragma unroll
            for (int i = 0; i < 8; i++) a1[i] = mul2(a1[i], f2);
            den1 *= f; m1 = s1v;
        }
        float p1 = __expf(s1v - m1);
        den1 += p1;
        u64 p12 = pack2(p1, p1);
        a1[0] = fma2(va.x, p12, a1[0]); a1[1] = fma2(va.y, p12, a1[1]);
        a1[2] = fma2(vb.x, p12, a1[2]); a1[3] = fma2(vb.y, p12, a1[3]);
        a1[4] = fma2(vc.x, p12, a1[4]); a1[5] = fma2(vc.y, p12, a1[5]);
        a1[6] = fma2(vd.x, p12, a1[6]); a1[7] = fma2(vd.y, p12, a1[7]);
    }

    size_t base = ((size_t)b*Cn + h*16)*Ln;
    float inv0 = 1.f/den0;
    #pragma unroll
    for (int i = 0; i < 8; i++){
        float z0, z1; unpack2(a0[i], z0, z1);
        g_scr[base + (size_t)(2*i  )*Ln + r0] = z0*inv0;
        g_scr[base + (size_t)(2*i+1)*Ln + r0] = z1*inv0;
    }
    if (ok1){
        float inv1 = 1.f/den1;
        #pragma unroll
        for (int i = 0; i < 8; i++){
            float z0, z1; unpack2(a1[i], z0, z1);
            g_scr[base + (size_t)(2*i  )*Ln + r1] = z0*inv1;
            g_scr[base + (size_t)(2*i+1)*Ln + r1] = z1*inv1;
        }
    }
}

// ---------------- host launcher ----------------
extern "C" void kernel_launch(void* const* d_in, const int* in_sizes, int n_in,
                              void* d_out, int out_size){
    (void)in_sizes; (void)n_in; (void)out_size;
    const float* x    = (const float*)d_in[0];
    const float* mask = (const float*)d_in[1];
    const float* dw_w = (const float*)d_in[2];
    const float* dw_b = (const float*)d_in[3];
    const float* pw_w = (const float*)d_in[4];
    const float* pw_b = (const float*)d_in[5];
    const float* wq   = (const float*)d_in[6];
    const float* bq   = (const float*)d_in[7];
    const float* wk   = (const float*)d_in[8];
    const float* bk   = (const float*)d_in[9];
    const float* wv   = (const float*)d_in[10];
    const float* bv   = (const float*)d_in[11];
    const float* wo   = (const float*)d_in[12];
    const float* bo   = (const float*)d_in[13];
    const float* fc_w = (const float*)d_in[14];
    const float* fc_b = (const float*)d_in[15];
    const float* ln_g = (const float*)d_in[16];
    const float* ln_b = (const float*)d_in[17];
    float* outp = (float*)d_out;

    float *bufA, *bufB, *scr;
    cudaGetSymbolAddress((void**)&bufA, g_bufA);
    cudaGetSymbolAddress((void**)&bufB, g_bufB);
    cudaGetSymbolAddress((void**)&scr,  g_scr);

    const int CONV_SMEM = CONV_SMEM_F * 4;
    const int MM_SMEM   = MM_SMEM_F * 4;
    const int ATTN_SMEM = ATTN_SMEM_F * 4;
    cudaFuncSetAttribute(k_conv, cudaFuncAttributeMaxDynamicSharedMemorySize, CONV_SMEM);
    cudaFuncSetAttribute(k_mm<false,false,true>,  cudaFuncAttributeMaxDynamicSharedMemorySize, MM_SMEM);
    cudaFuncSetAttribute(k_mm<true,true,false>,   cudaFuncAttributeMaxDynamicSharedMemorySize, MM_SMEM);
    cudaFuncSetAttribute(k_qkv, cudaFuncAttributeMaxDynamicSharedMemorySize, MM_SMEM);
    cudaFuncSetAttribute(k_attn, cudaFuncAttributeMaxDynamicSharedMemorySize, ATTN_SMEM);

    // stage 1: x + pos, LN stats
    k_pos<<<dim3(Bn, 50), 256>>>(x);
    k_fin<<<1, 64>>>(50);

    // stage 2: 4 fused conv layers (ping-pong)
    float* cin  = bufA;
    float* cout = bufB;
    for (int i = 0; i < 4; i++){
        k_conv<<<dim3(Bn, NLT), 256, CONV_SMEM>>>(cin, cout,
            dw_w + i*Cn*Kn, dw_b + i*Cn, pw_w + i*Cn*Cn, pw_b + i*Cn, ln_g, ln_b);
        k_fin<<<1, 64>>>(NLT);
        float* t = cin; cin = cout; cout = t;
    }
    // cin = residual after 4 conv layers; current stats in g_muvar

    // stage 3: attention
    k_qkv<<<dim3(Bn, NLT, 3), 256, MM_SMEM>>>(cin, wq, bq, wk, bk, wv, bv, ln_g, ln_b);
    k_attn<<<Bn*Hn, 256, ATTN_SMEM>>>(mask);
    k_mm<false,false,true><<<dim3(Bn, NLT), 256, MM_SMEM>>>(scr, cin, cout, wo, bo, nullptr, nullptr);
    k_fin<<<1, 64>>>(NLT);

    // stage 4: FC + relu + residual -> final output
    k_mm<true,true,false><<<dim3(Bn, NLT), 256, MM_SMEM>>>(cout, cout, outp, fc_w, fc_b, ln_g, ln_b);
}

// round 2
// speedup vs baseline: 1.3251x; 1.3251x over previous
#include <cuda_runtime.h>

#define Bn 64
#define Cn 128
#define Ln 400
#define Hn 8
#define Kn 7
#define CLn (Cn*Ln)            // 51200
#define BCL (Bn*Cn*Ln)         // 3276800
#define EPSf 1e-5f
#define LTILE 64
#define NLT2 7                 // ceil(400/64)

// ---------------- scratch (static device arrays; no allocation) ----------------
__device__ float g_bufA[BCL];
__device__ float g_bufB[BCL];
__device__ float g_scr[BCL];     // attention output (B,C,L)
__device__ float g_q[BCL];       // (B,H,L,DK)
__device__ float g_k[BCL];
__device__ float g_v[BCL];
__device__ float g_partA[Bn*64*2];
__device__ float g_partB[Bn*64*2];

// ---------------- packed f32x2 helpers ----------------
typedef unsigned long long u64;
__device__ __forceinline__ u64 pack2(float lo, float hi){
    u64 r; asm("mov.b64 %0, {%1,%2};" : "=l"(r) : "f"(lo), "f"(hi)); return r;
}
__device__ __forceinline__ void unpack2(u64 v, float& lo, float& hi){
    asm("mov.b64 {%0,%1}, %2;" : "=f"(lo), "=f"(hi) : "l"(v));
}
__device__ __forceinline__ u64 fma2(u64 a, u64 b, u64 c){
    u64 d; asm("fma.rn.f32x2 %0, %1, %2, %3;" : "=l"(d) : "l"(a), "l"(b), "l"(c)); return d;
}
__device__ __forceinline__ u64 mul2(u64 a, u64 b){
    u64 d; asm("mul.rn.f32x2 %0, %1, %2;" : "=l"(d) : "l"(a), "l"(b)); return d;
}

// deterministic 2-value block reduction (256 threads), writes [sum,sumsq] to out2
__device__ __forceinline__ void block_reduce2(float s, float ss, float* out2, float* red){
    #pragma unroll
    for (int o = 16; o > 0; o >>= 1){
        s  += __shfl_down_sync(0xffffffffu, s,  o);
        ss += __shfl_down_sync(0xffffffffu, ss, o);
    }
    int w = threadIdx.x >> 5;
    if ((threadIdx.x & 31) == 0){ red[w*2] = s; red[w*2+1] = ss; }
    __syncthreads();
    if (threadIdx.x == 0){
        float a = 0.f, b = 0.f;
        int nw = blockDim.x >> 5;
        for (int i = 0; i < nw; i++){ a += red[i*2]; b += red[i*2+1]; }
        out2[0] = a; out2[1] = b;
    }
}

// warp-0 computes mu/rsigma from partials into red[0],red[1] (requires later __syncthreads)
__device__ __forceinline__ void stats_from_parts(const float* partIn, int b, int nparts, float* red){
    if (threadIdx.x < 32){
        float s = 0.f, ss = 0.f;
        for (int i = threadIdx.x; i < nparts; i += 32){
            s  += partIn[(b*64+i)*2];
            ss += partIn[(b*64+i)*2+1];
        }
        #pragma unroll
        for (int o = 16; o > 0; o >>= 1){
            s  += __shfl_down_sync(0xffffffffu, s,  o);
            ss += __shfl_down_sync(0xffffffffu, ss, o);
        }
        if (threadIdx.x == 0){
            float mu  = s / (float)CLn;
            float var = ss / (float)CLn - mu*mu;
            red[0] = mu;
            red[1] = rsqrtf(var + EPSf);
        }
    }
}

// ---------------- kernel: x + positional encoding, + LN partial stats ----------------
__global__ __launch_bounds__(256) void k_pos(const float* __restrict__ x){
    int b  = blockIdx.x;
    int i4 = blockIdx.y * 256 + threadIdx.x;          // 0..12799
    float4 xv = ((const float4*)x)[b*(CLn/4) + i4];
    int e0 = i4 * 4;
    int c  = e0 / Ln;
    int l  = e0 - c * Ln;
    float fc, ph;
    if ((c & 1) == 0){ fc =  powf(10000.f, -(float)c / 128.f);        ph = 0.f; }
    else             { fc = -powf(10000.f, (1.f - (float)c) / 128.f); ph = 1.5707963267948966f; }
    float v0 = xv.x + sinf((float)(l+0)*fc + ph);
    float v1 = xv.y + sinf((float)(l+1)*fc + ph);
    float v2 = xv.z + sinf((float)(l+2)*fc + ph);
    float v3 = xv.w + sinf((float)(l+3)*fc + ph);
    ((float4*)g_bufA)[b*(CLn/4) + i4] = make_float4(v0, v1, v2, v3);
    float s  = v0 + v1 + v2 + v3;
    float ss = v0*v0 + v1*v1 + v2*v2 + v3*v3;
    __shared__ float red[16];
    block_reduce2(s, ss, &g_partA[(b*64 + blockIdx.y)*2], red);
}

// ---------------- fused conv layer ----------------
// grid (B, NLT2), block 256
#define CONV_SMEM_F (16896 + 9216 + 1024 + 128 + 16)
__global__ __launch_bounds__(256) void k_conv(
        const float* __restrict__ in, float* __restrict__ out,
        const float* __restrict__ dw, const float* __restrict__ db,
        const float* __restrict__ pw, const float* __restrict__ pb,
        const float* __restrict__ lng, const float* __restrict__ lnb,
        const float* __restrict__ partIn, float* __restrict__ partOut, int nparts){
    extern __shared__ float sm[];
    float* Wsm  = sm;                  // [c][o] pitch 132 : 16896
    float* XsmH = Wsm + 16896;         // [c][70] pitch 72 : 9216 (aliased by Ysm)
    float* Ysm  = XsmH;                // [c][64] pitch 66 : 8448
    float* Dw   = XsmH + 9216;         // [c][7] pitch 8
    float* Db   = Dw + 1024;
    float* red  = Db + 128;
    int b = blockIdx.x, lt = blockIdx.y, tid = threadIdx.x;
    int l0 = lt * LTILE;

    stats_from_parts(partIn, b, nparts, red);
    for (int idx = tid; idx < Cn*Cn; idx += 256){
        int o = idx >> 7, c = idx & 127;
        Wsm[c*132 + o] = pw[idx];
    }
    for (int idx = tid; idx < Cn*Kn; idx += 256)
        Dw[(idx/7)*8 + (idx - (idx/7)*7)] = dw[idx];
    if (tid < Cn) Db[tid] = db[tid];
    __syncthreads();
    float mu = red[0], rs = red[1];
    for (int idx = tid; idx < Cn*70; idx += 256){
        int c = idx / 70, j = idx - c*70;
        int gl = l0 - 3 + j;
        float v = 0.f;
        if (gl >= 0 && gl < Ln)
            v = (in[(b*Cn + c)*Ln + gl] - mu)*rs*lng[c*Ln + gl] + lnb[c*Ln + gl];
        XsmH[c*72 + j] = v;
    }
    __syncthreads();
    // depthwise into registers
    float yv[32];
    #pragma unroll
    for (int k = 0; k < 32; k++){
        int idx = k*256 + tid;
        int c = idx >> 6, l = idx & 63;
        float a = Db[c];
        #pragma unroll
        for (int t = 0; t < 7; t++) a += XsmH[c*72 + l + t] * Dw[c*8 + t];
        yv[k] = a;
    }
    __syncthreads();
    #pragma unroll
    for (int k = 0; k < 32; k++){
        int idx = k*256 + tid;
        int c = idx >> 6, l = idx & 63;
        Ysm[c*66 + l] = yv[k];
    }
    __syncthreads();

    int tx = tid & 31, ty = tid >> 5, ob = ty*16;
    u64 accA[8], accB[8];
    #pragma unroll
    for (int k = 0; k < 8; k++){ accA[k] = pack2(0.f,0.f); accB[k] = pack2(0.f,0.f); }
    #pragma unroll 4
    for (int c = 0; c < Cn; c++){
        float2 y = *(const float2*)(Ysm + c*66 + 2*tx);
        u64 y0 = pack2(y.x, y.x), y1 = pack2(y.y, y.y);
        const ulonglong2* wp = (const ulonglong2*)(Wsm + c*132 + ob);
        ulonglong2 wa = wp[0], wb = wp[1], wc2 = wp[2], wd = wp[3];
        accA[0]=fma2(wa.x ,y0,accA[0]); accB[0]=fma2(wa.x ,y1,accB[0]);
        accA[1]=fma2(wa.y ,y0,accA[1]); accB[1]=fma2(wa.y ,y1,accB[1]);
        accA[2]=fma2(wb.x ,y0,accA[2]); accB[2]=fma2(wb.x ,y1,accB[2]);
        accA[3]=fma2(wb.y ,y0,accA[3]); accB[3]=fma2(wb.y ,y1,accB[3]);
        accA[4]=fma2(wc2.x,y0,accA[4]); accB[4]=fma2(wc2.x,y1,accB[4]);
        accA[5]=fma2(wd.x ,y0,accA[5]); accB[5]=fma2(wd.x ,y1,accB[5]);
        accA[6]=fma2(wc2.y,y0,accA[6]); accB[6]=fma2(wc2.y,y1,accB[6]);
        accA[7]=fma2(wd.y ,y0,accA[7]); accB[7]=fma2(wd.y ,y1,accB[7]);
    }
    int col = l0 + 2*tx;
    float s = 0.f, ss = 0.f;
    if (col < Ln){
        const int omap[8] = {0, 2, 4, 6, 8, 12, 10, 14};
        #pragma unroll
        for (int k = 0; k < 8; k++){
            int o0 = ob + omap[k];
            float a0, a1, b0v, b1v;
            unpack2(accA[k], a0, a1);
            unpack2(accB[k], b0v, b1v);
            float p0 = pb[o0], p1 = pb[o0+1];
            a0 += p0; b0v += p0; a1 += p1; b1v += p1;
            a0  = a0  > 0.f ? a0  : 0.f;  b0v = b0v > 0.f ? b0v : 0.f;
            a1  = a1  > 0.f ? a1  : 0.f;  b1v = b1v > 0.f ? b1v : 0.f;
            float2 rr0 = *(const float2*)&in[(b*Cn + o0  )*Ln + col];
            float2 rr1 = *(const float2*)&in[(b*Cn + o0+1)*Ln + col];
            float v00 = rr0.x + a0, v01 = rr0.y + b0v;
            float v10 = rr1.x + a1, v11 = rr1.y + b1v;
            *(float2*)&out[(b*Cn + o0  )*Ln + col] = make_float2(v00, v01);
            *(float2*)&out[(b*Cn + o0+1)*Ln + col] = make_float2(v10, v11);
            s  += v00 + v01 + v10 + v11;
            ss += v00*v00 + v01*v01 + v10*v10 + v11*v11;
        }
    }
    block_reduce2(s, ss, &partOut[(b*64 + lt)*2], red);
}

// ---------------- generic matmul: out = resid + [relu](W @ [LN](in) + bias) ----------------
// grid (B, NLT2), block 256
#define MM_SMEM_F (16896 + 8448 + 16)
template<bool LN, bool RELU, bool STATS>
__global__ __launch_bounds__(256) void k_mm(
        const float* __restrict__ in, const float* resid, float* __restrict__ out,
        const float* __restrict__ W, const float* __restrict__ bias,
        const float* __restrict__ lng, const float* __restrict__ lnb,
        const float* __restrict__ partIn, float* __restrict__ partOut, int nparts){
    extern __shared__ float sm[];
    float* Wsm = sm;                 // [c][o] pitch 132
    float* Xsm = Wsm + 16896;        // [c][64] pitch 66
    float* red = Xsm + 8448;
    int b = blockIdx.x, lt = blockIdx.y, tid = threadIdx.x;
    int l0 = lt * LTILE;
    if (LN) stats_from_parts(partIn, b, nparts, red);
    for (int idx = tid; idx < Cn*Cn; idx += 256){
        int o = idx >> 7, c = idx & 127;
        Wsm[c*132 + o] = W[idx];
    }
    __syncthreads();
    float mu = 0.f, rs = 1.f;
    if (LN){ mu = red[0]; rs = red[1]; }
    for (int idx = tid; idx < Cn*64; idx += 256){
        int c = idx >> 6, j = idx & 63;
        int gl = l0 + j;
        float v = 0.f;
        if (gl < Ln){
            v = in[(b*Cn + c)*Ln + gl];
            if (LN) v = (v - mu)*rs*lng[c*Ln + gl] + lnb[c*Ln + gl];
        }
        Xsm[c*66 + j] = v;
    }
    __syncthreads();
    int tx = tid & 31, ty = tid >> 5, ob = ty*16;
    u64 accA[8], accB[8];
    #pragma unroll
    for (int k = 0; k < 8; k++){ accA[k] = pack2(0.f,0.f); accB[k] = pack2(0.f,0.f); }
    #pragma unroll 4
    for (int c = 0; c < Cn; c++){
        float2 y = *(const float2*)(Xsm + c*66 + 2*tx);
        u64 y0 = pack2(y.x, y.x), y1 = pack2(y.y, y.y);
        const ulonglong2* wp = (const ulonglong2*)(Wsm + c*132 + ob);
        ulonglong2 wa = wp[0], wb = wp[1], wc2 = wp[2], wd = wp[3];
        accA[0]=fma2(wa.x ,y0,accA[0]); accB[0]=fma2(wa.x ,y1,accB[0]);
        accA[1]=fma2(wa.y ,y0,accA[1]); accB[1]=fma2(wa.y ,y1,accB[1]);
        accA[2]=fma2(wb.x ,y0,accA[2]); accB[2]=fma2(wb.x ,y1,accB[2]);
        accA[3]=fma2(wb.y ,y0,accA[3]); accB[3]=fma2(wb.y ,y1,accB[3]);
        accA[4]=fma2(wc2.x,y0,accA[4]); accB[4]=fma2(wc2.x,y1,accB[4]);
        accA[5]=fma2(wd.x ,y0,accA[5]); accB[5]=fma2(wd.x ,y1,accB[5]);
        accA[6]=fma2(wc2.y,y0,accA[6]); accB[6]=fma2(wc2.y,y1,accB[6]);
        accA[7]=fma2(wd.y ,y0,accA[7]); accB[7]=fma2(wd.y ,y1,accB[7]);
    }
    int col = l0 + 2*tx;
    float s = 0.f, ss = 0.f;
    if (col < Ln){
        const int omap[8] = {0, 2, 4, 6, 8, 12, 10, 14};
        #pragma unroll
        for (int k = 0; k < 8; k++){
            int o0 = ob + omap[k];
            float a0, a1, b0v, b1v;
            unpack2(accA[k], a0, a1);
            unpack2(accB[k], b0v, b1v);
            float p0 = bias[o0], p1 = bias[o0+1];
            a0 += p0; b0v += p0; a1 += p1; b1v += p1;
            if (RELU){
                a0  = a0  > 0.f ? a0  : 0.f;  b0v = b0v > 0.f ? b0v : 0.f;
                a1  = a1  > 0.f ? a1  : 0.f;  b1v = b1v > 0.f ? b1v : 0.f;
            }
            float2 rr0 = *(const float2*)&resid[(b*Cn + o0  )*Ln + col];
            float2 rr1 = *(const float2*)&resid[(b*Cn + o0+1)*Ln + col];
            float v00 = rr0.x + a0, v01 = rr0.y + b0v;
            float v10 = rr1.x + a1, v11 = rr1.y + b1v;
            *(float2*)&out[(b*Cn + o0  )*Ln + col] = make_float2(v00, v01);
            *(float2*)&out[(b*Cn + o0+1)*Ln + col] = make_float2(v10, v11);
            if (STATS){
                s  += v00 + v01 + v10 + v11;
                ss += v00*v00 + v01*v01 + v10*v10 + v11*v11;
            }
        }
    }
    if (STATS) block_reduce2(s, ss, &partOut[(b*64 + lt)*2], red);
}

// ---------------- QKV projections (with LN on input), writes (B,H,L,DK) ----------------
// grid (B, NLT2, 3)
__global__ __launch_bounds__(256) void k_qkv(
        const float* __restrict__ in,
        const float* __restrict__ wq, const float* __restrict__ bq,
        const float* __restrict__ wk, const float* __restrict__ bk,
        const float* __restrict__ wv, const float* __restrict__ bv,
        const float* __restrict__ lng, const float* __restrict__ lnb,
        const float* __restrict__ partIn, int nparts){
    extern __shared__ float sm[];
    float* Wsm = sm;
    float* Xsm = Wsm + 16896;
    float* red = Xsm + 8448;
    int which = blockIdx.z;
    const float* W    = which == 0 ? wq : (which == 1 ? wk : wv);
    const float* bias = which == 0 ? bq : (which == 1 ? bk : bv);
    float* outp       = which == 0 ? g_q : (which == 1 ? g_k : g_v);
    float scale = which == 0 ? 0.08838834764831845f : 1.f;   // 1/sqrt(C)
    int b = blockIdx.x, lt = blockIdx.y, tid = threadIdx.x;
    int l0 = lt * LTILE;
    stats_from_parts(partIn, b, nparts, red);
    for (int idx = tid; idx < Cn*Cn; idx += 256){
        int o = idx >> 7, c = idx & 127;
        Wsm[c*132 + o] = W[idx];
    }
    __syncthreads();
    float mu = red[0], rs = red[1];
    for (int idx = tid; idx < Cn*64; idx += 256){
        int c = idx >> 6, j = idx & 63;
        int gl = l0 + j;
        float v = 0.f;
        if (gl < Ln)
            v = (in[(b*Cn + c)*Ln + gl] - mu)*rs*lng[c*Ln + gl] + lnb[c*Ln + gl];
        Xsm[c*66 + j] = v;
    }
    __syncthreads();
    int tx = tid & 31, ty = tid >> 5, ob = ty*16;
    u64 accA[8], accB[8];
    #pragma unroll
    for (int k = 0; k < 8; k++){ accA[k] = pack2(0.f,0.f); accB[k] = pack2(0.f,0.f); }
    #pragma unroll 4
    for (int c = 0; c < Cn; c++){
        float2 y = *(const float2*)(Xsm + c*66 + 2*tx);
        u64 y0 = pack2(y.x, y.x), y1 = pack2(y.y, y.y);
        const ulonglong2* wp = (const ulonglong2*)(Wsm + c*132 + ob);
        ulonglong2 wa = wp[0], wb = wp[1], wc2 = wp[2], wd = wp[3];
        accA[0]=fma2(wa.x ,y0,accA[0]); accB[0]=fma2(wa.x ,y1,accB[0]);
        accA[1]=fma2(wa.y ,y0,accA[1]); accB[1]=fma2(wa.y ,y1,accB[1]);
        accA[2]=fma2(wb.x ,y0,accA[2]); accB[2]=fma2(wb.x ,y1,accB[2]);
        accA[3]=fma2(wb.y ,y0,accA[3]); accB[3]=fma2(wb.y ,y1,accB[3]);
        accA[4]=fma2(wc2.x,y0,accA[4]); accB[4]=fma2(wc2.x,y1,accB[4]);
        accA[5]=fma2(wd.x ,y0,accA[5]); accB[5]=fma2(wd.x ,y1,accB[5]);
        accA[6]=fma2(wc2.y,y0,accA[6]); accB[6]=fma2(wc2.y,y1,accB[6]);
        accA[7]=fma2(wd.y ,y0,accA[7]); accB[7]=fma2(wd.y ,y1,accB[7]);
    }
    int col = l0 + 2*tx;
    if (col < Ln){
        const int omap[8] = {0, 2, 4, 6, 8, 12, 10, 14};
        float* opA = outp + ((size_t)(b*Hn + ty)*Ln + col)*16;
        float* opB = opA + 16;
        #pragma unroll
        for (int k = 0; k < 8; k++){
            int d0 = omap[k];
            float a0, a1, b0v, b1v;
            unpack2(accA[k], a0, a1);
            unpack2(accB[k], b0v, b1v);
            float p0 = bias[ob + d0], p1 = bias[ob + d0 + 1];
            *(float2*)(opA + d0) = make_float2((a0 + p0)*scale, (a1 + p1)*scale);
            *(float2*)(opB + d0) = make_float2((b0v + p0)*scale, (b1v + p1)*scale);
        }
    }
}

// ---------------- attention: per (b,h), online softmax, K/V in smem ----------------
// grid (B*H), block 256 ; rows 2*tid, 2*tid+1 for tid<200
#define ATTN_SMEM_F (Ln*16 + Ln*16 + Ln)
__global__ __launch_bounds__(256) void k_attn(const float* __restrict__ mask){
    extern __shared__ float sm[];
    float* Ksm = sm;
    float* Vsm = Ksm + Ln*16;
    float* Msm = Vsm + Ln*16;
    int bh = blockIdx.x;
    int b = bh >> 3, h = bh & 7;
    int tid = threadIdx.x;
    const float4* kp = (const float4*)(g_k + (size_t)bh*Ln*16);
    const float4* vp = (const float4*)(g_v + (size_t)bh*Ln*16);
    for (int i = tid; i < Ln*4; i += 256){
        ((float4*)Ksm)[i] = kp[i];
        ((float4*)Vsm)[i] = vp[i];
    }
    for (int i = tid; i < Ln; i += 256) Msm[i] = mask[b*Ln + i];
    __syncthreads();

    if (tid >= 200) return;
    int r0 = 2*tid, r1 = 2*tid + 1;
    u64 q0[8], q1[8];
    {
        const u64* qp = (const u64*)(g_q + ((size_t)bh*Ln + r0)*16);
        #pragma unroll
        for (int i = 0; i < 8; i++) q0[i] = qp[i];
        const u64* qp1 = (const u64*)(g_q + ((size_t)bh*Ln + r1)*16);
        #pragma unroll
        for (int i = 0; i < 8; i++) q1[i] = qp1[i];
    }

    float m0 = -3.0e38f, m1 = -3.0e38f, den0 = 0.f, den1 = 0.f;
    u64 a0[8], a1[8];
    #pragma unroll
    for (int i = 0; i < 8; i++){ a0[i] = pack2(0.f,0.f); a1[i] = pack2(0.f,0.f); }

    for (int j = 0; j < Ln; j++){
        const ulonglong2* kr = (const ulonglong2*)(Ksm + j*16);
        ulonglong2 ka = kr[0], kb = kr[1], kc = kr[2], kd = kr[3];
        u64 s2;
        s2 = mul2(q0[0], ka.x);      s2 = fma2(q0[1], ka.y, s2);
        s2 = fma2(q0[2], kb.x, s2);  s2 = fma2(q0[3], kb.y, s2);
        s2 = fma2(q0[4], kc.x, s2);  s2 = fma2(q0[5], kc.y, s2);
        s2 = fma2(q0[6], kd.x, s2);  s2 = fma2(q0[7], kd.y, s2);
        float lo, hi; unpack2(s2, lo, hi);
        float s0 = lo + hi;
        s2 = mul2(q1[0], ka.x);      s2 = fma2(q1[1], ka.y, s2);
        s2 = fma2(q1[2], kb.x, s2);  s2 = fma2(q1[3], kb.y, s2);
        s2 = fma2(q1[4], kc.x, s2);  s2 = fma2(q1[5], kc.y, s2);
        s2 = fma2(q1[6], kd.x, s2);  s2 = fma2(q1[7], kd.y, s2);
        unpack2(s2, lo, hi);
        float s1v = lo + hi;

        float mk  = Msm[j];
        float adj = (1.f - mk)*(-1e30f);
        s0  = s0 *mk + adj;
        s1v = s1v*mk + adj;

        const ulonglong2* vr = (const ulonglong2*)(Vsm + j*16);
        ulonglong2 va = vr[0], vb = vr[1], vc = vr[2], vd = vr[3];

        if (s0 > m0){
            float f = __expf(m0 - s0);
            u64 f2 = pack2(f, f);
            #pragma unroll
            for (int i = 0; i < 8; i++) a0[i] = mul2(a0[i], f2);
            den0 *= f; m0 = s0;
        }
        float p0 = __expf(s0 - m0);
        den0 += p0;
        u64 p02 = pack2(p0, p0);
        a0[0] = fma2(va.x, p02, a0[0]); a0[1] = fma2(va.y, p02, a0[1]);
        a0[2] = fma2(vb.x, p02, a0[2]); a0[3] = fma2(vb.y, p02, a0[3]);
        a0[4] = fma2(vc.x, p02, a0[4]); a0[5] = fma2(vc.y, p02, a0[5]);
        a0[6] = fma2(vd.x, p02, a0[6]); a0[7] = fma2(vd.y, p02, a0[7]);

        if (s1v > m1){
            float f = __expf(m1 - s1v);
            u64 f2 = pack2(f, f);
            #pragma unroll
            for (int i = 0; i < 8; i++) a1[i] = mul2(a1[i], f2);
            den1 *= f; m1 = s1v;
        }
        float p1 = __expf(s1v - m1);
        den1 += p1;
        u64 p12 = pack2(p1, p1);
        a1[0] = fma2(va.x, p12, a1[0]); a1[1] = fma2(va.y, p12, a1[1]);
        a1[2] = fma2(vb.x, p12, a1[2]); a1[3] = fma2(vb.y, p12, a1[3]);
        a1[4] = fma2(vc.x, p12, a1[4]); a1[5] = fma2(vc.y, p12, a1[5]);
        a1[6] = fma2(vd.x, p12, a1[6]); a1[7] = fma2(vd.y, p12, a1[7]);
    }

    // write: channel ch = 2i (+lane), cols (r0, r1) adjacent -> float2 stores
    size_t base = ((size_t)b*Cn + h*16)*Ln;
    float inv0 = 1.f/den0;
    float inv1 = 1.f/den1;
    #pragma unroll
    for (int i = 0; i < 8; i++){
        float z00, z01, z10, z11;
        unpack2(a0[i], z00, z01);   // row r0, channels 2i, 2i+1
        unpack2(a1[i], z10, z11);   // row r1, channels 2i, 2i+1
        *(float2*)&g_scr[base + (size_t)(2*i  )*Ln + r0] = make_float2(z00*inv0, z10*inv1);
        *(float2*)&g_scr[base + (size_t)(2*i+1)*Ln + r0] = make_float2(z01*inv0, z11*inv1);
    }
}

// ---------------- host launcher ----------------
extern "C" void kernel_launch(void* const* d_in, const int* in_sizes, int n_in,
                              void* d_out, int out_size){
    (void)in_sizes; (void)n_in; (void)out_size;
    const float* x    = (const float*)d_in[0];
    const float* mask = (const float*)d_in[1];
    const float* dw_w = (const float*)d_in[2];
    const float* dw_b = (const float*)d_in[3];
    const float* pw_w = (const float*)d_in[4];
    const float* pw_b = (const float*)d_in[5];
    const float* wq   = (const float*)d_in[6];
    const float* bq   = (const float*)d_in[7];
    const float* wk   = (const float*)d_in[8];
    const float* bk   = (const float*)d_in[9];
    const float* wv   = (const float*)d_in[10];
    const float* bv   = (const float*)d_in[11];
    const float* wo   = (const float*)d_in[12];
    const float* bo   = (const float*)d_in[13];
    const float* fc_w = (const float*)d_in[14];
    const float* fc_b = (const float*)d_in[15];
    const float* ln_g = (const float*)d_in[16];
    const float* ln_b = (const float*)d_in[17];
    float* outp = (float*)d_out;

    float *bufA, *bufB, *scr, *pA, *pB;
    cudaGetSymbolAddress((void**)&bufA, g_bufA);
    cudaGetSymbolAddress((void**)&bufB, g_bufB);
    cudaGetSymbolAddress((void**)&scr,  g_scr);
    cudaGetSymbolAddress((void**)&pA,   g_partA);
    cudaGetSymbolAddress((void**)&pB,   g_partB);

    const int CONV_SMEM = CONV_SMEM_F * 4;
    const int MM_SMEM   = MM_SMEM_F * 4;
    const int ATTN_SMEM = ATTN_SMEM_F * 4;
    cudaFuncSetAttribute(k_conv, cudaFuncAttributeMaxDynamicSharedMemorySize, CONV_SMEM);
    cudaFuncSetAttribute(k_mm<false,false,true>,  cudaFuncAttributeMaxDynamicSharedMemorySize, MM_SMEM);
    cudaFuncSetAttribute(k_mm<true,true,false>,   cudaFuncAttributeMaxDynamicSharedMemorySize, MM_SMEM);
    cudaFuncSetAttribute(k_qkv, cudaFuncAttributeMaxDynamicSharedMemorySize, MM_SMEM);
    cudaFuncSetAttribute(k_attn, cudaFuncAttributeMaxDynamicSharedMemorySize, ATTN_SMEM);

    // stage 1: x + pos, LN partials -> pA
    k_pos<<<dim3(Bn, 50), 256>>>(x);

    // stage 2: 4 fused conv layers (ping-pong buffers AND ping-pong partials)
    float* cin  = bufA;
    float* cout = bufB;
    const float* pin = pA;
    float* pout = pB;
    int nparts = 50;
    for (int i = 0; i < 4; i++){
        k_conv<<<dim3(Bn, NLT2), 256, CONV_SMEM>>>(cin, cout,
            dw_w + i*Cn*Kn, dw_b + i*Cn, pw_w + i*Cn*Cn, pw_b + i*Cn, ln_g, ln_b,
            pin, pout, nparts);
        float* t = cin; cin = cout; cout = t;
        float* tp = (float*)pin; pin = pout; pout = tp;
        nparts = NLT2;
    }
    // cin = residual after 4 conv layers; stats partials in pin (nparts=7)

    // stage 3: attention
    k_qkv<<<dim3(Bn, NLT2, 3), 256, MM_SMEM>>>(cin, wq, bq, wk, bk, wv, bv, ln_g, ln_b, pin, nparts);
    k_attn<<<Bn*Hn, 256, ATTN_SMEM>>>(mask);
    // o-proj: out = resid + W@scr ; produce stats into pout
    k_mm<false,false,true><<<dim3(Bn, NLT2), 256, MM_SMEM>>>(scr, cin, cout, wo, bo,
        nullptr, nullptr, nullptr, pout, 0);

    // stage 4: FC + relu + residual -> final output (reads stats from pout)
    k_mm<true,true,false><<<dim3(Bn, NLT2), 256, MM_SMEM>>>(cout, cout, outp, fc_w, fc_b,
        ln_g, ln_b, pout, nullptr, NLT2);
}

// round 3
// speedup vs baseline: 1.4216x; 1.0728x over previous
#include <cuda_runtime.h>

#define Bn 64
#define Cn 128
#define Ln 400
#define Hn 8
#define Kn 7
#define CLn (Cn*Ln)            // 51200
#define BCL (Bn*Cn*Ln)         // 3276800
#define EPSf 1e-5f
#define LTILE 64
#define NLT2 7                 // ceil(400/64)

// ---------------- scratch (static device arrays; no allocation) ----------------
__device__ float g_bufA[BCL];
__device__ float g_bufB[BCL];
__device__ float g_scr[BCL];     // attention output (B,C,L)
__device__ float g_q[BCL];       // (B,H,L,DK)
__device__ float g_k[BCL];
__device__ float g_v[BCL];
__device__ float g_partA[Bn*64*2];
__device__ float g_partB[Bn*64*2];

// ---------------- packed f32x2 helpers ----------------
typedef unsigned long long u64;
__device__ __forceinline__ u64 pack2(float lo, float hi){
    u64 r; asm("mov.b64 %0, {%1,%2};" : "=l"(r) : "f"(lo), "f"(hi)); return r;
}
__device__ __forceinline__ void unpack2(u64 v, float& lo, float& hi){
    asm("mov.b64 {%0,%1}, %2;" : "=f"(lo), "=f"(hi) : "l"(v));
}
__device__ __forceinline__ u64 fma2(u64 a, u64 b, u64 c){
    u64 d; asm("fma.rn.f32x2 %0, %1, %2, %3;" : "=l"(d) : "l"(a), "l"(b), "l"(c)); return d;
}
__device__ __forceinline__ u64 mul2(u64 a, u64 b){
    u64 d; asm("mul.rn.f32x2 %0, %1, %2;" : "=l"(d) : "l"(a), "l"(b)); return d;
}

// deterministic 2-value block reduction, writes [sum,sumsq] to out2. red: >= 2*nwarps floats
__device__ __forceinline__ void block_reduce2(float s, float ss, float* out2, float* red){
    #pragma unroll
    for (int o = 16; o > 0; o >>= 1){
        s  += __shfl_down_sync(0xffffffffu, s,  o);
        ss += __shfl_down_sync(0xffffffffu, ss, o);
    }
    int w = threadIdx.x >> 5;
    if ((threadIdx.x & 31) == 0){ red[w*2] = s; red[w*2+1] = ss; }
    __syncthreads();
    if (threadIdx.x == 0){
        float a = 0.f, b = 0.f;
        int nw = blockDim.x >> 5;
        for (int i = 0; i < nw; i++){ a += red[i*2]; b += red[i*2+1]; }
        out2[0] = a; out2[1] = b;
    }
}

// warp-0 computes mu/rsigma from partials into red[0],red[1] (needs later __syncthreads)
__device__ __forceinline__ void stats_from_parts(const float* partIn, int b, int nparts, float* red){
    if (threadIdx.x < 32){
        float s = 0.f, ss = 0.f;
        for (int i = threadIdx.x; i < nparts; i += 32){
            s  += partIn[(b*64+i)*2];
            ss += partIn[(b*64+i)*2+1];
        }
        #pragma unroll
        for (int o = 16; o > 0; o >>= 1){
            s  += __shfl_down_sync(0xffffffffu, s,  o);
            ss += __shfl_down_sync(0xffffffffu, ss, o);
        }
        if (threadIdx.x == 0){
            float mu  = s / (float)CLn;
            float var = ss / (float)CLn - mu*mu;
            red[0] = mu;
            red[1] = rsqrtf(var + EPSf);
        }
    }
}

// ---------------- kernel: x + positional encoding, + LN partial stats ----------------
__global__ __launch_bounds__(256) void k_pos(const float* __restrict__ x){
    int b  = blockIdx.x;
    int i4 = blockIdx.y * 256 + threadIdx.x;          // 0..12799
    float4 xv = ((const float4*)x)[b*(CLn/4) + i4];
    int e0 = i4 * 4;
    int c  = e0 / Ln;
    int l  = e0 - c * Ln;
    float fc, ph;
    if ((c & 1) == 0){ fc =  powf(10000.f, -(float)c / 128.f);        ph = 0.f; }
    else             { fc = -powf(10000.f, (1.f - (float)c) / 128.f); ph = 1.5707963267948966f; }
    float v0 = xv.x + sinf((float)(l+0)*fc + ph);
    float v1 = xv.y + sinf((float)(l+1)*fc + ph);
    float v2 = xv.z + sinf((float)(l+2)*fc + ph);
    float v3 = xv.w + sinf((float)(l+3)*fc + ph);
    ((float4*)g_bufA)[b*(CLn/4) + i4] = make_float4(v0, v1, v2, v3);
    float s  = v0 + v1 + v2 + v3;
    float ss = v0*v0 + v1*v1 + v2*v2 + v3*v3;
    __shared__ float red[16];
    block_reduce2(s, ss, &g_partA[(b*64 + blockIdx.y)*2], red);
}

// ================= GEMM mainloop (shared shape) ==========================
// 512 threads, 16 warps. warp w: out-channels 8w..8w+7 ; lane tx: cols 2tx,2tx+1
// acc[p][j]: channels (8w+2p, 8w+2p+1), col j.
#define GEMM_MAIN(XS, XPITCH)                                               \
    int tx = tid & 31, w = tid >> 5;                                        \
    u64 acc[4][2];                                                          \
    _Pragma("unroll")                                                       \
    for (int p = 0; p < 4; p++){ acc[p][0] = 0ULL; acc[p][1] = 0ULL; }      \
    _Pragma("unroll 4")                                                     \
    for (int c = 0; c < Cn; c++){                                           \
        float2 y = *(const float2*)((XS) + c*(XPITCH) + 2*tx);              \
        u64 y0 = pack2(y.x, y.x), y1 = pack2(y.y, y.y);                     \
        const ulonglong2* wp = (const ulonglong2*)(Wsm + c*132 + w*8);      \
        ulonglong2 wa = wp[0], wb = wp[1];                                  \
        acc[0][0] = fma2(wa.x, y0, acc[0][0]);                              \
        acc[0][1] = fma2(wa.x, y1, acc[0][1]);                              \
        acc[1][0] = fma2(wa.y, y0, acc[1][0]);                              \
        acc[1][1] = fma2(wa.y, y1, acc[1][1]);                              \
        acc[2][0] = fma2(wb.x, y0, acc[2][0]);                              \
        acc[2][1] = fma2(wb.x, y1, acc[2][1]);                              \
        acc[3][0] = fma2(wb.y, y0, acc[3][0]);                              \
        acc[3][1] = fma2(wb.y, y1, acc[3][1]);                              \
    }

// ---------------- fused conv layer ----------------
// grid (B, NLT2), block 512
// smem floats: W 16896 | XsmH 9216 (pitch 72, 70 cols; Ysm pitch 64 aliased) | Dw 1024 | Db 128 | red 32
#define CONV_SMEM_F (16896 + 9216 + 1024 + 128 + 32)
__global__ __launch_bounds__(512, 2) void k_conv(
        const float* __restrict__ in, float* __restrict__ out,
        const float* __restrict__ dw, const float* __restrict__ db,
        const float* __restrict__ pw, const float* __restrict__ pb,
        const float* __restrict__ lng, const float* __restrict__ lnb,
        const float* __restrict__ partIn, float* __restrict__ partOut, int nparts){
    extern __shared__ float sm[];
    float* Wsm  = sm;
    float* XsmH = Wsm + 16896;         // [c][70] pitch 72
    float* Ysm  = XsmH;                // [c][64] pitch 64 (aliased)
    float* Dw   = XsmH + 9216;         // [c][7] pitch 8
    float* Db   = Dw + 1024;
    float* red  = Db + 128;
    int b = blockIdx.x, lt = blockIdx.y, tid = threadIdx.x;
    int l0 = lt * LTILE;

    stats_from_parts(partIn, b, nparts, red);
    for (int idx = tid; idx < Cn*Cn; idx += 512){
        int o = idx >> 7, c = idx & 127;
        Wsm[c*132 + o] = pw[idx];
    }
    for (int idx = tid; idx < Cn*Kn; idx += 512)
        Dw[(idx/7)*8 + (idx - (idx/7)*7)] = dw[idx];
    if (tid < Cn) Db[tid] = db[tid];
    __syncthreads();
    float mu = red[0], rs = red[1];
    for (int idx = tid; idx < Cn*70; idx += 512){
        int c = idx / 70, j = idx - c*70;
        int gl = l0 - 3 + j;
        float v = 0.f;
        if (gl >= 0 && gl < Ln)
            v = (in[(b*Cn + c)*Ln + gl] - mu)*rs*lng[c*Ln + gl] + lnb[c*Ln + gl];
        XsmH[c*72 + j] = v;
    }
    __syncthreads();
    // depthwise, two c-halves (row-disjoint aliasing), 8 regs
    float yv[8];
    #pragma unroll
    for (int k = 0; k < 8; k++){           // rows 0..63
        int idx = k*512 + tid;
        int c = idx >> 6, l = idx & 63;
        float a = Db[c];
        #pragma unroll
        for (int t = 0; t < 7; t++) a += XsmH[c*72 + l + t] * Dw[c*8 + t];
        yv[k] = a;
    }
    __syncthreads();
    {
        // write rows 0..63, then compute rows 64..127 (disjoint rows)
        float yw[8];
        #pragma unroll
        for (int k = 0; k < 8; k++){
            int idx = k*512 + tid;
            int c = idx >> 6, l = idx & 63;
            Ysm[c*64 + l] = yv[k];
        }
        #pragma unroll
        for (int k = 0; k < 8; k++){       // rows 64..127
            int idx = 4096 + k*512 + tid;
            int c = idx >> 6, l = idx & 63;
            float a = Db[c];
            #pragma unroll
            for (int t = 0; t < 7; t++) a += XsmH[c*72 + l + t] * Dw[c*8 + t];
            yw[k] = a;
        }
        __syncthreads();
        #pragma unroll
        for (int k = 0; k < 8; k++){
            int idx = 4096 + k*512 + tid;
            int c = idx >> 6, l = idx & 63;
            Ysm[c*64 + l] = yw[k];
        }
    }
    __syncthreads();

    GEMM_MAIN(Ysm, 64)

    int col = l0 + 2*tx;
    float s = 0.f, ss = 0.f;
    if (col < Ln){
        #pragma unroll
        for (int p = 0; p < 4; p++){
            int o = w*8 + 2*p;
            float aL, aH, bL, bH;
            unpack2(acc[p][0], aL, aH);    // col : (o, o+1)
            unpack2(acc[p][1], bL, bH);    // col+1 : (o, o+1)
            float bo0 = pb[o], bo1 = pb[o+1];
            float z00 = aL + bo0, z01 = bL + bo0;
            float z10 = aH + bo1, z11 = bH + bo1;
            z00 = z00 > 0.f ? z00 : 0.f;  z01 = z01 > 0.f ? z01 : 0.f;
            z10 = z10 > 0.f ? z10 : 0.f;  z11 = z11 > 0.f ? z11 : 0.f;
            float2 r0 = *(const float2*)&in[(b*Cn + o  )*Ln + col];
            float2 r1 = *(const float2*)&in[(b*Cn + o+1)*Ln + col];
            float v00 = r0.x + z00, v01 = r0.y + z01;
            float v10 = r1.x + z10, v11 = r1.y + z11;
            *(float2*)&out[(b*Cn + o  )*Ln + col] = make_float2(v00, v01);
            *(float2*)&out[(b*Cn + o+1)*Ln + col] = make_float2(v10, v11);
            s  += v00 + v01 + v10 + v11;
            ss += v00*v00 + v01*v01 + v10*v10 + v11*v11;
        }
    }
    block_reduce2(s, ss, &partOut[(b*64 + lt)*2], red);
}

// ---------------- generic matmul: out = resid + [relu](W @ [LN](in) + bias) ----------------
// grid (B, NLT2), block 512
#define MM_SMEM_F (16896 + 8192 + 32)
template<bool LN, bool RELU, bool STATS>
__global__ __launch_bounds__(512, 2) void k_mm(
        const float* __restrict__ in, const float* resid, float* __restrict__ out,
        const float* __restrict__ W, const float* __restrict__ bias,
        const float* __restrict__ lng, const float* __restrict__ lnb,
        const float* __restrict__ partIn, float* __restrict__ partOut, int nparts){
    extern __shared__ float sm[];
    float* Wsm = sm;                 // [c][o] pitch 132
    float* Xsm = Wsm + 16896;        // [c][64] pitch 64
    float* red = Xsm + 8192;
    int b = blockIdx.x, lt = blockIdx.y, tid = threadIdx.x;
    int l0 = lt * LTILE;
    if (LN) stats_from_parts(partIn, b, nparts, red);
    for (int idx = tid; idx < Cn*Cn; idx += 512){
        int o = idx >> 7, c = idx & 127;
        Wsm[c*132 + o] = W[idx];
    }
    __syncthreads();
    float mu = 0.f, rs = 1.f;
    if (LN){ mu = red[0]; rs = red[1]; }
    for (int idx = tid; idx < Cn*64; idx += 512){
        int c = idx >> 6, j = idx & 63;
        int gl = l0 + j;
        float v = 0.f;
        if (gl < Ln){
            v = in[(b*Cn + c)*Ln + gl];
            if (LN) v = (v - mu)*rs*lng[c*Ln + gl] + lnb[c*Ln + gl];
        }
        Xsm[c*64 + j] = v;
    }
    __syncthreads();

    GEMM_MAIN(Xsm, 64)

    int col = l0 + 2*tx;
    float s = 0.f, ss = 0.f;
    if (col < Ln){
        #pragma unroll
        for (int p = 0; p < 4; p++){
            int o = w*8 + 2*p;
            float aL, aH, bL, bH;
            unpack2(acc[p][0], aL, aH);
            unpack2(acc[p][1], bL, bH);
            float bo0 = bias[o], bo1 = bias[o+1];
            float z00 = aL + bo0, z01 = bL + bo0;
            float z10 = aH + bo1, z11 = bH + bo1;
            if (RELU){
                z00 = z00 > 0.f ? z00 : 0.f;  z01 = z01 > 0.f ? z01 : 0.f;
                z10 = z10 > 0.f ? z10 : 0.f;  z11 = z11 > 0.f ? z11 : 0.f;
            }
            float2 r0 = *(const float2*)&resid[(b*Cn + o  )*Ln + col];
            float2 r1 = *(const float2*)&resid[(b*Cn + o+1)*Ln + col];
            float v00 = r0.x + z00, v01 = r0.y + z01;
            float v10 = r1.x + z10, v11 = r1.y + z11;
            *(float2*)&out[(b*Cn + o  )*Ln + col] = make_float2(v00, v01);
            *(float2*)&out[(b*Cn + o+1)*Ln + col] = make_float2(v10, v11);
            if (STATS){
                s  += v00 + v01 + v10 + v11;
                ss += v00*v00 + v01*v01 + v10*v10 + v11*v11;
            }
        }
    }
    if (STATS) block_reduce2(s, ss, &partOut[(b*64 + lt)*2], red);
}

// ---------------- QKV projections (LN on input), writes (B,H,L,DK) ----------------
// grid (B, NLT2, 3), block 512
__global__ __launch_bounds__(512, 2) void k_qkv(
        const float* __restrict__ in,
        const float* __restrict__ wq, const float* __restrict__ bq,
        const float* __restrict__ wk, const float* __restrict__ bk,
        const float* __restrict__ wv, const float* __restrict__ bv,
        const float* __restrict__ lng, const float* __restrict__ lnb,
        const float* __restrict__ partIn, int nparts){
    extern __shared__ float sm[];
    float* Wsm = sm;
    float* Xsm = Wsm + 16896;
    float* red = Xsm + 8192;
    int which = blockIdx.z;
    const float* W    = which == 0 ? wq : (which == 1 ? wk : wv);
    const float* bias = which == 0 ? bq : (which == 1 ? bk : bv);
    float* outp       = which == 0 ? g_q : (which == 1 ? g_k : g_v);
    float scale = which == 0 ? 0.08838834764831845f : 1.f;   // 1/sqrt(C)
    int b = blockIdx.x, lt = blockIdx.y, tid = threadIdx.x;
    int l0 = lt * LTILE;
    stats_from_parts(partIn, b, nparts, red);
    for (int idx = tid; idx < Cn*Cn; idx += 512){
        int o = idx >> 7, c = idx & 127;
        Wsm[c*132 + o] = W[idx];
    }
    __syncthreads();
    float mu = red[0], rs = red[1];
    for (int idx = tid; idx < Cn*64; idx += 512){
        int c = idx >> 6, j = idx & 63;
        int gl = l0 + j;
        float v = 0.f;
        if (gl < Ln)
            v = (in[(b*Cn + c)*Ln + gl] - mu)*rs*lng[c*Ln + gl] + lnb[c*Ln + gl];
        Xsm[c*64 + j] = v;
    }
    __syncthreads();

    GEMM_MAIN(Xsm, 64)

    int col = l0 + 2*tx;
    if (col < Ln){
        int h  = w >> 1;           // head
        int db = (w & 1) * 8;      // dim base within head
        float* opA = outp + ((size_t)(b*Hn + h)*Ln + col)*16 + db;
        float* opB = opA + 16;     // col+1
        #pragma unroll
        for (int p = 0; p < 4; p++){
            float aL, aH, bL, bH;
            unpack2(acc[p][0], aL, aH);
            unpack2(acc[p][1], bL, bH);
            int o = w*8 + 2*p;
            float bo0 = bias[o], bo1 = bias[o+1];
            *(float2*)(opA + 2*p) = make_float2((aL + bo0)*scale, (aH + bo1)*scale);
            *(float2*)(opB + 2*p) = make_float2((bL + bo0)*scale, (bH + bo1)*scale);
        }
    }
}

// ---------------- attention: per (b,h), online softmax, 1 row/thread ----------------
// grid (B*H), block 416 (rows 0..399 active)
#define ATTN_SMEM_F (Ln*16 + Ln*16 + Ln)
__global__ __launch_bounds__(416) void k_attn(const float* __restrict__ mask){
    extern __shared__ float sm[];
    float* Ksm = sm;
    float* Vsm = Ksm + Ln*16;
    float* Msm = Vsm + Ln*16;
    int bh = blockIdx.x;
    int b = bh >> 3, h = bh & 7;
    int tid = threadIdx.x;
    const float4* kp = (const float4*)(g_k + (size_t)bh*Ln*16);
    const float4* vp = (const float4*)(g_v + (size_t)bh*Ln*16);
    for (int i = tid; i < Ln*4; i += 416){
        ((float4*)Ksm)[i] = kp[i];
        ((float4*)Vsm)[i] = vp[i];
    }
    for (int i = tid; i < Ln; i += 416) Msm[i] = mask[b*Ln + i];
    __syncthreads();

    if (tid >= Ln) return;
    int r = tid;
    u64 q[8];
    {
        const u64* qp = (const u64*)(g_q + ((size_t)bh*Ln + r)*16);
        #pragma unroll
        for (int i = 0; i < 8; i++) q[i] = qp[i];
    }

    float m = -3.0e38f, den = 0.f;
    u64 a[8];
    #pragma unroll
    for (int i = 0; i < 8; i++) a[i] = 0ULL;

    for (int j = 0; j < Ln; j++){
        const ulonglong2* kr = (const ulonglong2*)(Ksm + j*16);
        ulonglong2 ka = kr[0], kb = kr[1], kc = kr[2], kd = kr[3];
        u64 s2;
        s2 = mul2(q[0], ka.x);      s2 = fma2(q[1], ka.y, s2);
        s2 = fma2(q[2], kb.x, s2);  s2 = fma2(q[3], kb.y, s2);
        s2 = fma2(q[4], kc.x, s2);  s2 = fma2(q[5], kc.y, s2);
        s2 = fma2(q[6], kd.x, s2);  s2 = fma2(q[7], kd.y, s2);
        float lo, hi; unpack2(s2, lo, hi);
        float sc = lo + hi;

        float mk  = Msm[j];
        sc = sc*mk + (1.f - mk)*(-1e30f);

        const ulonglong2* vr = (const ulonglong2*)(Vsm + j*16);
        ulonglong2 va = vr[0], vb = vr[1], vc = vr[2], vd = vr[3];

        if (sc > m){
            float f = __expf(m - sc);
            u64 f2 = pack2(f, f);
            #pragma unroll
            for (int i = 0; i < 8; i++) a[i] = mul2(a[i], f2);
            den *= f; m = sc;
        }
        float p = __expf(sc - m);
        den += p;
        u64 p2 = pack2(p, p);
        a[0] = fma2(va.x, p2, a[0]); a[1] = fma2(va.y, p2, a[1]);
        a[2] = fma2(vb.x, p2, a[2]); a[3] = fma2(vb.y, p2, a[3]);
        a[4] = fma2(vc.x, p2, a[4]); a[5] = fma2(vc.y, p2, a[5]);
        a[6] = fma2(vd.x, p2, a[6]); a[7] = fma2(vd.y, p2, a[7]);
    }

    size_t base = ((size_t)b*Cn + h*16)*Ln + r;
    float inv = 1.f/den;
    #pragma unroll
    for (int i = 0; i < 8; i++){
        float z0, z1; unpack2(a[i], z0, z1);
        g_scr[base + (size_t)(2*i  )*Ln] = z0*inv;
        g_scr[base + (size_t)(2*i+1)*Ln] = z1*inv;
    }
}

// ---------------- host launcher ----------------
extern "C" void kernel_launch(void* const* d_in, const int* in_sizes, int n_in,
                              void* d_out, int out_size){
    (void)in_sizes; (void)n_in; (void)out_size;
    const float* x    = (const float*)d_in[0];
    const float* mask = (const float*)d_in[1];
    const float* dw_w = (const float*)d_in[2];
    const float* dw_b = (const float*)d_in[3];
    const float* pw_w = (const float*)d_in[4];
    const float* pw_b = (const float*)d_in[5];
    const float* wq   = (const float*)d_in[6];
    const float* bq   = (const float*)d_in[7];
    const float* wk   = (const float*)d_in[8];
    const float* bk   = (const float*)d_in[9];
    const float* wv   = (const float*)d_in[10];
    const float* bv   = (const float*)d_in[11];
    const float* wo   = (const float*)d_in[12];
    const float* bo   = (const float*)d_in[13];
    const float* fc_w = (const float*)d_in[14];
    const float* fc_b = (const float*)d_in[15];
    const float* ln_g = (const float*)d_in[16];
    const float* ln_b = (const float*)d_in[17];
    float* outp = (float*)d_out;

    float *bufA, *bufB, *scr, *pA, *pB;
    cudaGetSymbolAddress((void**)&bufA, g_bufA);
    cudaGetSymbolAddress((void**)&bufB, g_bufB);
    cudaGetSymbolAddress((void**)&scr,  g_scr);
    cudaGetSymbolAddress((void**)&pA,   g_partA);
    cudaGetSymbolAddress((void**)&pB,   g_partB);

    const int CONV_SMEM = CONV_SMEM_F * 4;
    const int MM_SMEM   = MM_SMEM_F * 4;
    const int ATTN_SMEM = ATTN_SMEM_F * 4;
    cudaFuncSetAttribute(k_conv, cudaFuncAttributeMaxDynamicSharedMemorySize, CONV_SMEM);
    cudaFuncSetAttribute(k_mm<false,false,true>,  cudaFuncAttributeMaxDynamicSharedMemorySize, MM_SMEM);
    cudaFuncSetAttribute(k_mm<true,true,false>,   cudaFuncAttributeMaxDynamicSharedMemorySize, MM_SMEM);
    cudaFuncSetAttribute(k_qkv, cudaFuncAttributeMaxDynamicSharedMemorySize, MM_SMEM);
    cudaFuncSetAttribute(k_attn, cudaFuncAttributeMaxDynamicSharedMemorySize, ATTN_SMEM);

    // stage 1: x + pos, LN partials -> pA
    k_pos<<<dim3(Bn, 50), 256>>>(x);

    // stage 2: 4 fused conv layers (ping-pong buffers AND ping-pong partials)
    float* cin  = bufA;
    float* cout = bufB;
    const float* pin = pA;
    float* pout = pB;
    int nparts = 50;
    for (int i = 0; i < 4; i++){
        k_conv<<<dim3(Bn, NLT2), 512, CONV_SMEM>>>(cin, cout,
            dw_w + i*Cn*Kn, dw_b + i*Cn, pw_w + i*Cn*Cn, pw_b + i*Cn, ln_g, ln_b,
            pin, pout, nparts);
        float* t = cin; cin = cout; cout = t;
        float* tp = (float*)pin; pin = pout; pout = tp;
        nparts = NLT2;
    }
    // cin = residual after 4 conv layers; stats partials in pin (nparts=7)

    // stage 3: attention
    k_qkv<<<dim3(Bn, NLT2, 3), 512, MM_SMEM>>>(cin, wq, bq, wk, bk, wv, bv, ln_g, ln_b, pin, nparts);
    k_attn<<<Bn*Hn, 416, ATTN_SMEM>>>(mask);
    // o-proj: out = resid + W@scr ; stats -> pout
    k_mm<false,false,true><<<dim3(Bn, NLT2), 512, MM_SMEM>>>(scr, cin, cout, wo, bo,
        nullptr, nullptr, nullptr, pout, 0);

    // stage 4: FC + relu + residual -> final output (stats from pout)
    k_mm<true,true,false><<<dim3(Bn, NLT2), 512, MM_SMEM>>>(cout, cout, outp, fc_w, fc_b,
        ln_g, ln_b, pout, nullptr, NLT2);
}

// round 4
// speedup vs baseline: 1.5399x; 1.0833x over previous
#include <cuda_runtime.h>

#define Bn 64
#define Cn 128
#define Ln 400
#define Hn 8
#define Kn 7
#define CLn (Cn*Ln)            // 51200
#define BCL (Bn*Cn*Ln)         // 3276800
#define EPSf 1e-5f
#define LTILE 32
#define NLT 13                 // ceil(400/32)
#define QSCALE 0.08838834764831845f

// ---------------- scratch (static device arrays; no allocation) ----------------
__device__ float g_bufA[BCL];
__device__ float g_bufB[BCL];
__device__ float g_scr[BCL];     // attention output (B,C,L)
__device__ float g_q[BCL];       // (B,H,L,DK)
__device__ float g_k[BCL];
__device__ float g_v[BCL];
__device__ float g_partA[Bn*64*2];
__device__ float g_partB[Bn*64*2];
__device__ float g_wt[9*Cn*Cn]; // transposed weights [m][c][o]: pw0..3, wq(scaled), wk, wv, wo, fc
__device__ float g_bqs[Cn];     // scaled bq

// ---------------- packed f32x2 helpers ----------------
typedef unsigned long long u64;
__device__ __forceinline__ u64 pack2(float lo, float hi){
    u64 r; asm("mov.b64 %0, {%1,%2};" : "=l"(r) : "f"(lo), "f"(hi)); return r;
}
__device__ __forceinline__ void unpack2(u64 v, float& lo, float& hi){
    asm("mov.b64 {%0,%1}, %2;" : "=f"(lo), "=f"(hi) : "l"(v));
}
__device__ __forceinline__ u64 fma2(u64 a, u64 b, u64 c){
    u64 d; asm("fma.rn.f32x2 %0, %1, %2, %3;" : "=l"(d) : "l"(a), "l"(b), "l"(c)); return d;
}
__device__ __forceinline__ u64 mul2(u64 a, u64 b){
    u64 d; asm("mul.rn.f32x2 %0, %1, %2;" : "=l"(d) : "l"(a), "l"(b)); return d;
}

// deterministic 2-value block reduction, writes [sum,sumsq] to out2. red >= 2*nwarps floats
__device__ __forceinline__ void block_reduce2(float s, float ss, float* out2, float* red){
    #pragma unroll
    for (int o = 16; o > 0; o >>= 1){
        s  += __shfl_down_sync(0xffffffffu, s,  o);
        ss += __shfl_down_sync(0xffffffffu, ss, o);
    }
    int w = threadIdx.x >> 5;
    if ((threadIdx.x & 31) == 0){ red[w*2] = s; red[w*2+1] = ss; }
    __syncthreads();
    if (threadIdx.x == 0){
        float a = 0.f, b = 0.f;
        int nw = blockDim.x >> 5;
        for (int i = 0; i < nw; i++){ a += red[i*2]; b += red[i*2+1]; }
        out2[0] = a; out2[1] = b;
    }
}

// warp-0 computes mu/rsigma from partials into red[0],red[1] (needs later __syncthreads)
__device__ __forceinline__ void stats_from_parts(const float* partIn, int b, int nparts, float* red){
    if (threadIdx.x < 32){
        float s = 0.f, ss = 0.f;
        for (int i = threadIdx.x; i < nparts; i += 32){
            s  += partIn[(b*64+i)*2];
            ss += partIn[(b*64+i)*2+1];
        }
        #pragma unroll
        for (int o = 16; o > 0; o >>= 1){
            s  += __shfl_down_sync(0xffffffffu, s,  o);
            ss += __shfl_down_sync(0xffffffffu, ss, o);
        }
        if (threadIdx.x == 0){
            float mu  = s / (float)CLn;
            float var = ss / (float)CLn - mu*mu;
            red[0] = mu;
            red[1] = rsqrtf(var + EPSf);
        }
    }
}

// ---------------- prep: transpose weights ----------------
__global__ __launch_bounds__(256) void k_prep(
        const float* __restrict__ pw, const float* __restrict__ wq,
        const float* __restrict__ wk, const float* __restrict__ wv,
        const float* __restrict__ wo, const float* __restrict__ fcw,
        const float* __restrict__ bq){
    int idx = blockIdx.x*256 + threadIdx.x;
    if (idx < 9*Cn*Cn){
        int m = idx >> 14, r = idx & 16383;
        int o = r >> 7, c = r & 127;
        const float* src = (m < 4) ? (pw + m*Cn*Cn) :
                           (m == 4) ? wq : (m == 5) ? wk : (m == 6) ? wv :
                           (m == 7) ? wo : fcw;
        float v = src[o*Cn + c];
        if (m == 4) v *= QSCALE;
        g_wt[m*Cn*Cn + c*Cn + o] = v;
    }
    if (idx < Cn) g_bqs[idx] = bq[idx] * QSCALE;
}

// ---------------- kernel: x + positional encoding, + LN partial stats ----------------
__global__ __launch_bounds__(256) void k_pos(const float* __restrict__ x){
    __shared__ float fr[Cn], phs[Cn];
    __shared__ float red[16];
    int tid = threadIdx.x;
    if (tid < Cn){
        int c = tid;
        if ((c & 1) == 0){ fr[c] =  powf(10000.f, -(float)c/128.f);       phs[c] = 0.f; }
        else             { fr[c] = -powf(10000.f, (1.f-(float)c)/128.f);  phs[c] = 1.5707963267948966f; }
    }
    __syncthreads();
    int b  = blockIdx.x;
    int i4 = blockIdx.y * 256 + tid;                  // 0..12799
    float4 xv = ((const float4*)x)[b*(CLn/4) + i4];
    int e0 = i4 * 4;
    int c  = e0 / Ln;
    int l  = e0 - c * Ln;
    float fc = fr[c], ph = phs[c];
    float v0 = xv.x + sinf((float)(l+0)*fc + ph);
    float v1 = xv.y + sinf((float)(l+1)*fc + ph);
    float v2 = xv.z + sinf((float)(l+2)*fc + ph);
    float v3 = xv.w + sinf((float)(l+3)*fc + ph);
    ((float4*)g_bufA)[b*(CLn/4) + i4] = make_float4(v0, v1, v2, v3);
    float s  = v0 + v1 + v2 + v3;
    float ss = v0*v0 + v1*v1 + v2*v2 + v3*v3;
    block_reduce2(s, ss, &g_partA[(b*64 + blockIdx.y)*2], red);
}

// ================= GEMM mainloop (layout: lane=4 out-ch via LDG.128, warp=8 cols bcast) ===
// 128 threads, 4 warps. warp w: cols 8w..8w+7 ; lane tx: out-channels 4tx..4tx+3
// acc[i][j]: channel 4tx+i, cols (8w+2j, 8w+2j+1).
#define GEMM_CORE(WTp, XS)                                                    \
    int tx = tid & 31, w = tid >> 5;                                          \
    u64 acc[4][4];                                                            \
    _Pragma("unroll")                                                         \
    for (int i = 0; i < 4; i++){                                              \
        _Pragma("unroll")                                                     \
        for (int j = 0; j < 4; j++) acc[i][j] = 0ULL;                         \
    }                                                                         \
    {                                                                         \
        const float4* wp = ((const float4*)(WTp)) + tx;                       \
        const float*  xb = (XS) + 8*w;                                        \
        _Pragma("unroll 4")                                                   \
        for (int c = 0; c < Cn; c++){                                         \
            float4 w4 = wp[c*32];                                             \
            ulonglong2 xA = *(const ulonglong2*)(xb + c*LTILE);               \
            ulonglong2 xB = *(const ulonglong2*)(xb + c*LTILE + 4);           \
            u64 W0 = pack2(w4.x, w4.x), W1 = pack2(w4.y, w4.y);               \
            u64 W2 = pack2(w4.z, w4.z), W3 = pack2(w4.w, w4.w);               \
            acc[0][0]=fma2(W0,xA.x,acc[0][0]); acc[0][1]=fma2(W0,xA.y,acc[0][1]); \
            acc[0][2]=fma2(W0,xB.x,acc[0][2]); acc[0][3]=fma2(W0,xB.y,acc[0][3]); \
            acc[1][0]=fma2(W1,xA.x,acc[1][0]); acc[1][1]=fma2(W1,xA.y,acc[1][1]); \
            acc[1][2]=fma2(W1,xB.x,acc[1][2]); acc[1][3]=fma2(W1,xB.y,acc[1][3]); \
            acc[2][0]=fma2(W2,xA.x,acc[2][0]); acc[2][1]=fma2(W2,xA.y,acc[2][1]); \
            acc[2][2]=fma2(W2,xB.x,acc[2][2]); acc[2][3]=fma2(W2,xB.y,acc[2][3]); \
            acc[3][0]=fma2(W3,xA.x,acc[3][0]); acc[3][1]=fma2(W3,xA.y,acc[3][1]); \
            acc[3][2]=fma2(W3,xB.x,acc[3][2]); acc[3][3]=fma2(W3,xB.y,acc[3][3]); \
        }                                                                     \
    }

// ---------------- fused conv layer ----------------
// grid (B, NLT), block 128
// smem floats: XsmH [c][38] pitch 40 = 5120 (Ysm [c][32] pitch 32 aliased) | Dw 1024 | Db 128 | red 16
#define CONV_SMEM_F (5120 + 1024 + 128 + 16)
__global__ __launch_bounds__(128, 6) void k_conv(
        const float* __restrict__ in, float* __restrict__ out,
        const float* __restrict__ Wt,
        const float* __restrict__ dw, const float* __restrict__ db,
        const float* __restrict__ pb,
        const float* __restrict__ lng, const float* __restrict__ lnb,
        const float* __restrict__ partIn, float* __restrict__ partOut, int nparts){
    extern __shared__ float sm[];
    float* XsmH = sm;                  // [c][38] pitch 40
    float* Ysm  = sm;                  // [c][32] pitch 32 (aliased)
    float* Dw   = sm + 5120;           // [c][7] pitch 8
    float* Db   = Dw + 1024;
    float* red  = Db + 128;
    int b = blockIdx.x, lt = blockIdx.y, tid = threadIdx.x;
    int l0 = lt * LTILE;

    stats_from_parts(partIn, b, nparts, red);
    for (int idx = tid; idx < Cn*Kn; idx += 128)
        Dw[(idx/7)*8 + (idx - (idx/7)*7)] = dw[idx];
    if (tid < Cn) Db[tid] = db[tid];
    __syncthreads();
    float mu = red[0], rs = red[1];
    for (int idx = tid; idx < Cn*38; idx += 128){
        int c = idx / 38, j = idx - c*38;
        int gl = l0 - 3 + j;
        float v = 0.f;
        if (gl >= 0 && gl < Ln)
            v = (in[(b*Cn + c)*Ln + gl] - mu)*rs*lng[c*Ln + gl] + lnb[c*Ln + gl];
        XsmH[c*40 + j] = v;
    }
    __syncthreads();
    // depthwise: phase A = channels 0..63 (reads XsmH rows 0..63 = [0,2560+38))
    float ya[16];
    #pragma unroll
    for (int k = 0; k < 16; k++){
        int idx = k*128 + tid;                 // 0..2047
        int c = idx >> 5, l = idx & 31;
        float a = Db[c];
        #pragma unroll
        for (int t = 0; t < 7; t++) a += XsmH[c*40 + l + t] * Dw[c*8 + t];
        ya[k] = a;
    }
    __syncthreads();
    {
        // write A to Ysm [0,2048) ; compute B from XsmH rows 64..127 ([2560,5120)) - disjoint
        float yb[16];
        #pragma unroll
        for (int k = 0; k < 16; k++){
            int idx = k*128 + tid;
            Ysm[idx] = ya[k];                  // Ysm[c*32+l] with idx = c*32+l (c<64)
        }
        #pragma unroll
        for (int k = 0; k < 16; k++){
            int idx = 2048 + k*128 + tid;      // channels 64..127
            int c = idx >> 5, l = idx & 31;
            float a = Db[c];
            #pragma unroll
            for (int t = 0; t < 7; t++) a += XsmH[c*40 + l + t] * Dw[c*8 + t];
            yb[k] = a;
        }
        __syncthreads();
        #pragma unroll
        for (int k = 0; k < 16; k++){
            int idx = 2048 + k*128 + tid;
            Ysm[idx] = yb[k];
        }
    }
    __syncthreads();

    GEMM_CORE(Wt, Ysm)

    int colBase = l0 + 8*w;
    float s = 0.f, ss = 0.f;
    if (colBase < Ln){
        float4 b4 = *(const float4*)&pb[4*tx];
        float bias[4] = {b4.x, b4.y, b4.z, b4.w};
        #pragma unroll
        for (int i = 0; i < 4; i++){
            int o = 4*tx + i;
            const float* rr = &in[(b*Cn + o)*Ln + colBase];
            float* oo = &out[(b*Cn + o)*Ln + colBase];
            #pragma unroll
            for (int j = 0; j < 4; j++){
                float z0, z1; unpack2(acc[i][j], z0, z1);
                z0 += bias[i]; z1 += bias[i];
                z0 = z0 > 0.f ? z0 : 0.f;  z1 = z1 > 0.f ? z1 : 0.f;
                float2 r = *(const float2*)(rr + 2*j);
                float v0 = r.x + z0, v1 = r.y + z1;
                *(float2*)(oo + 2*j) = make_float2(v0, v1);
                s += v0 + v1; ss += v0*v0 + v1*v1;
            }
        }
    }
    block_reduce2(s, ss, &partOut[(b*64 + lt)*2], red);
}

// ---------------- generic matmul: out = resid + [relu](W @ [LN](in) + bias) ----------------
// grid (B, NLT), block 128
#define MM_SMEM_F (4096 + 16)
template<bool LN, bool RELU, bool STATS>
__global__ __launch_bounds__(128, 6) void k_mm(
        const float* __restrict__ in, const float* resid, float* __restrict__ out,
        const float* __restrict__ Wt, const float* __restrict__ bias,
        const float* __restrict__ lng, const float* __restrict__ lnb,
        const float* __restrict__ partIn, float* __restrict__ partOut, int nparts){
    extern __shared__ float sm[];
    float* Xsm = sm;                 // [c][32] pitch 32
    float* red = sm + 4096;
    int b = blockIdx.x, lt = blockIdx.y, tid = threadIdx.x;
    int l0 = lt * LTILE;
    if (LN) stats_from_parts(partIn, b, nparts, red);
    __syncthreads();
    float mu = 0.f, rs = 1.f;
    if (LN){ mu = red[0]; rs = red[1]; }
    for (int idx = tid; idx < Cn*LTILE; idx += 128){
        int c = idx >> 5, j = idx & 31;
        int gl = l0 + j;
        float v = 0.f;
        if (gl < Ln){
            v = in[(b*Cn + c)*Ln + gl];
            if (LN) v = (v - mu)*rs*lng[c*Ln + gl] + lnb[c*Ln + gl];
        }
        Xsm[idx] = v;
    }
    __syncthreads();

    GEMM_CORE(Wt, Xsm)

    int colBase = l0 + 8*w;
    float s = 0.f, ss = 0.f;
    if (colBase < Ln){
        float4 b4 = *(const float4*)&bias[4*tx];
        float bi[4] = {b4.x, b4.y, b4.z, b4.w};
        #pragma unroll
        for (int i = 0; i < 4; i++){
            int o = 4*tx + i;
            const float* rr = &resid[(b*Cn + o)*Ln + colBase];
            float* oo = &out[(b*Cn + o)*Ln + colBase];
            #pragma unroll
            for (int j = 0; j < 4; j++){
                float z0, z1; unpack2(acc[i][j], z0, z1);
                z0 += bi[i]; z1 += bi[i];
                if (RELU){ z0 = z0 > 0.f ? z0 : 0.f;  z1 = z1 > 0.f ? z1 : 0.f; }
                float2 r = *(const float2*)(rr + 2*j);
                float v0 = r.x + z0, v1 = r.y + z1;
                *(float2*)(oo + 2*j) = make_float2(v0, v1);
                if (STATS){ s += v0 + v1; ss += v0*v0 + v1*v1; }
            }
        }
    }
    if (STATS) block_reduce2(s, ss, &partOut[(b*64 + lt)*2], red);
}

// ---------------- QKV projections (LN on input), writes (B,H,L,DK) ----------------
// grid (B, NLT, 3), block 128
__global__ __launch_bounds__(128, 6) void k_qkv(
        const float* __restrict__ in,
        const float* __restrict__ bq_s, const float* __restrict__ bk,
        const float* __restrict__ bv,
        const float* __restrict__ lng, const float* __restrict__ lnb,
        const float* __restrict__ partIn, int nparts){
    extern __shared__ float sm[];
    float* Xsm = sm;
    float* red = sm + 4096;
    int which = blockIdx.z;
    const float* Wt   = g_wt + (4 + which)*Cn*Cn;
    const float* bias = which == 0 ? bq_s : (which == 1 ? bk : bv);
    float* outp       = which == 0 ? g_q : (which == 1 ? g_k : g_v);
    int b = blockIdx.x, lt = blockIdx.y, tid = threadIdx.x;
    int l0 = lt * LTILE;
    stats_from_parts(partIn, b, nparts, red);
    __syncthreads();
    float mu = red[0], rs = red[1];
    for (int idx = tid; idx < Cn*LTILE; idx += 128){
        int c = idx >> 5, j = idx & 31;
        int gl = l0 + j;
        float v = 0.f;
        if (gl < Ln)
            v = (in[(b*Cn + c)*Ln + gl] - mu)*rs*lng[c*Ln + gl] + lnb[c*Ln + gl];
        Xsm[idx] = v;
    }
    __syncthreads();

    GEMM_CORE(Wt, Xsm)

    int colBase = l0 + 8*w;
    if (colBase < Ln){
        float4 b4 = *(const float4*)&bias[4*tx];
        int h  = tx >> 2;
        int dq = (tx & 3) * 4;
        float* basep = outp + ((size_t)(b*Hn + h)*Ln + colBase)*16 + dq;
        #pragma unroll
        for (int j = 0; j < 4; j++){
            float z00, z01, z10, z11, z20, z21, z30, z31;
            unpack2(acc[0][j], z00, z01);
            unpack2(acc[1][j], z10, z11);
            unpack2(acc[2][j], z20, z21);
            unpack2(acc[3][j], z30, z31);
            float* p = basep + (2*j)*16;
            *(float4*)p        = make_float4(z00 + b4.x, z10 + b4.y, z20 + b4.z, z30 + b4.w);
            *(float4*)(p + 16) = make_float4(z01 + b4.x, z11 + b4.y, z21 + b4.z, z31 + b4.w);
        }
    }
}

// ---------------- attention: per (b,h), online softmax, 1 row/thread ----------------
// grid (B*H), block 416 (rows 0..399 active)
#define ATTN_SMEM_F (Ln*16 + Ln*16 + Ln)
__global__ __launch_bounds__(416) void k_attn(const float* __restrict__ mask){
    extern __shared__ float sm[];
    float* Ksm = sm;
    float* Vsm = Ksm + Ln*16;
    float* Msm = Vsm + Ln*16;
    int bh = blockIdx.x;
    int b = bh >> 3, h = bh & 7;
    int tid = threadIdx.x;
    const float4* kp = (const float4*)(g_k + (size_t)bh*Ln*16);
    const float4* vp = (const float4*)(g_v + (size_t)bh*Ln*16);
    for (int i = tid; i < Ln*4; i += 416){
        ((float4*)Ksm)[i] = kp[i];
        ((float4*)Vsm)[i] = vp[i];
    }
    for (int i = tid; i < Ln; i += 416) Msm[i] = mask[b*Ln + i];
    __syncthreads();

    if (tid >= Ln) return;
    int r = tid;
    u64 q[8];
    {
        const u64* qp = (const u64*)(g_q + ((size_t)bh*Ln + r)*16);
        #pragma unroll
        for (int i = 0; i < 8; i++) q[i] = qp[i];
    }

    float m = -3.0e38f, den = 0.f;
    u64 a[8];
    #pragma unroll
    for (int i = 0; i < 8; i++) a[i] = 0ULL;

    for (int j = 0; j < Ln; j++){
        const ulonglong2* kr = (const ulonglong2*)(Ksm + j*16);
        ulonglong2 ka = kr[0], kb = kr[1], kc = kr[2], kd = kr[3];
        u64 s2;
        s2 = mul2(q[0], ka.x);      s2 = fma2(q[1], ka.y, s2);
        s2 = fma2(q[2], kb.x, s2);  s2 = fma2(q[3], kb.y, s2);
        s2 = fma2(q[4], kc.x, s2);  s2 = fma2(q[5], kc.y, s2);
        s2 = fma2(q[6], kd.x, s2);  s2 = fma2(q[7], kd.y, s2);
        float lo, hi; unpack2(s2, lo, hi);
        float sc = lo + hi;

        float mk  = Msm[j];
        sc = sc*mk + (1.f - mk)*(-1e30f);

        const ulonglong2* vr = (const ulonglong2*)(Vsm + j*16);
        ulonglong2 va = vr[0], vb = vr[1], vc = vr[2], vd = vr[3];

        if (sc > m){
            float f = __expf(m - sc);
            u64 f2 = pack2(f, f);
            #pragma unroll
            for (int i = 0; i < 8; i++) a[i] = mul2(a[i], f2);
            den *= f; m = sc;
        }
        float p = __expf(sc - m);
        den += p;
        u64 p2 = pack2(p, p);
        a[0] = fma2(va.x, p2, a[0]); a[1] = fma2(va.y, p2, a[1]);
        a[2] = fma2(vb.x, p2, a[2]); a[3] = fma2(vb.y, p2, a[3]);
        a[4] = fma2(vc.x, p2, a[4]); a[5] = fma2(vc.y, p2, a[5]);
        a[6] = fma2(vd.x, p2, a[6]); a[7] = fma2(vd.y, p2, a[7]);
    }

    size_t base = ((size_t)b*Cn + h*16)*Ln + r;
    float inv = 1.f/den;
    #pragma unroll
    for (int i = 0; i < 8; i++){
        float z0, z1; unpack2(a[i], z0, z1);
        g_scr[base + (size_t)(2*i  )*Ln] = z0*inv;
        g_scr[base + (size_t)(2*i+1)*Ln] = z1*inv;
    }
}

// ---------------- host launcher ----------------
extern "C" void kernel_launch(void* const* d_in, const int* in_sizes, int n_in,
                              void* d_out, int out_size){
    (void)in_sizes; (void)n_in; (void)out_size;
    const float* x    = (const float*)d_in[0];
    const float* mask = (const float*)d_in[1];
    const float* dw_w = (const float*)d_in[2];
    const float* dw_b = (const float*)d_in[3];
    const float* pw_w = (const float*)d_in[4];
    const float* pw_b = (const float*)d_in[5];
    const float* wq   = (const float*)d_in[6];
    const float* bq   = (const float*)d_in[7];
    const float* wk   = (const float*)d_in[8];
    const float* bk   = (const float*)d_in[9];
    const float* wv   = (const float*)d_in[10];
    const float* bv   = (const float*)d_in[11];
    const float* wo   = (const float*)d_in[12];
    const float* bo   = (const float*)d_in[13];
    const float* fc_w = (const float*)d_in[14];
    const float* fc_b = (const float*)d_in[15];
    const float* ln_g = (const float*)d_in[16];
    const float* ln_b = (const float*)d_in[17];
    float* outp = (float*)d_out;

    float *bufA, *bufB, *scr, *pA, *pB, *wt, *bqs;
    cudaGetSymbolAddress((void**)&bufA, g_bufA);
    cudaGetSymbolAddress((void**)&bufB, g_bufB);
    cudaGetSymbolAddress((void**)&scr,  g_scr);
    cudaGetSymbolAddress((void**)&pA,   g_partA);
    cudaGetSymbolAddress((void**)&pB,   g_partB);
    cudaGetSymbolAddress((void**)&wt,   g_wt);
    cudaGetSymbolAddress((void**)&bqs,  g_bqs);

    const int CONV_SMEM = CONV_SMEM_F * 4;
    const int MM_SMEM   = MM_SMEM_F * 4;
    const int ATTN_SMEM = ATTN_SMEM_F * 4;
    cudaFuncSetAttribute(k_attn, cudaFuncAttributeMaxDynamicSharedMemorySize, ATTN_SMEM);

    // stage 0: weight transposes
    k_prep<<<(9*Cn*Cn + 255)/256, 256>>>(pw_w, wq, wk, wv, wo, fc_w, bq);

    // stage 1: x + pos, LN partials -> pA
    k_pos<<<dim3(Bn, 50), 256>>>(x);

    // stage 2: 4 fused conv layers (ping-pong buffers AND ping-pong partials)
    float* cin  = bufA;
    float* cout = bufB;
    const float* pin = pA;
    float* pout = pB;
    int nparts = 50;
    for (int i = 0; i < 4; i++){
        k_conv<<<dim3(Bn, NLT), 128, CONV_SMEM>>>(cin, cout,
            wt + i*Cn*Cn, dw_w + i*Cn*Kn, dw_b + i*Cn, pw_b + i*Cn, ln_g, ln_b,
            pin, pout, nparts);
        float* t = cin; cin = cout; cout = t;
        float* tp = (float*)pin; pin = pout; pout = tp;
        nparts = NLT;
    }
    // cin = residual after 4 conv layers; stats partials in pin (nparts=13)

    // stage 3: attention
    k_qkv<<<dim3(Bn, NLT, 3), 128, MM_SMEM>>>(cin, bqs, bk, bv, ln_g, ln_b, pin, nparts);
    k_attn<<<Bn*Hn, 416, ATTN_SMEM>>>(mask);
    // o-proj: out = resid + W@scr ; stats -> pout
    k_mm<false,false,true><<<dim3(Bn, NLT), 128, MM_SMEM>>>(scr, cin, cout,
        wt + 7*Cn*Cn, bo, nullptr, nullptr, nullptr, pout, 0);

    // stage 4: FC + relu + residual -> final output (stats from pout)
    k_mm<true,true,false><<<dim3(Bn, NLT), 128, MM_SMEM>>>(cout, cout, outp,
        wt + 8*Cn*Cn, fc_b, ln_g, ln_b, pout, nullptr, NLT);
}